// round 7
// baseline (speedup 1.0000x reference)
#include <cuda_runtime.h>
#include <math.h>

#define B 64
#define T 128
#define V 25
#define C 128
#define K 128
#define R 32

// ---------------- scratch (device globals; no allocations allowed) ----------
__device__ float g_xbar[B*V*C];
__device__ float g_phi [B*V*K];
__device__ float g_theta[B*V*K];
__device__ float g_Hbar[B*V*K];
__device__ float g_Atil[B*V*V*K];      // [b][u][v][k]
__device__ float g_gate[B*K];
__device__ float g_H[B*T*V*K];         // [b][t][v][k]

// f32x2 packed FMA (SASS FFMA2) -- exact fp32, 2x rate
__device__ __forceinline__ unsigned long long fma2(unsigned long long a,
                                                   unsigned long long b,
                                                   unsigned long long c) {
    unsigned long long d;
    asm("fma.rn.f32x2 %0, %1, %2, %3;" : "=l"(d) : "l"(a), "l"(b), "l"(c));
    return d;
}
__device__ __forceinline__ void unpack2(unsigned long long p, float& lo, float& hi) {
    asm("mov.b64 {%0,%1}, %2;" : "=f"(lo), "=f"(hi) : "l"(p));
}

// ---------------- K1: xbar = mean_t x  --------------------------------------
__global__ void k1_xbar(const float* __restrict__ x) {
    int bv = blockIdx.x;
    int c  = threadIdx.x;
    int b = bv / V, v = bv % V;
    const float* p = x + ((size_t)(b*T)*V + v)*C + c;
    float acc = 0.f;
#pragma unroll 8
    for (int t = 0; t < T; t++) acc += p[(size_t)t*V*C];
    g_xbar[bv*C + c] = acc * (1.0f/T);
}

// ---------------- K2: phi_x / theta_x / Hbar  (xbar @ W + b) ----------------
__global__ void k2_small(const float* __restrict__ pw, const float* __restrict__ pb,
                         const float* __restrict__ tw, const float* __restrict__ tb,
                         const float* __restrict__ xw, const float* __restrict__ xb2) {
    extern __shared__ float sm2[];
    float* xb_s = sm2;            // 3200
    float* W_s  = sm2 + 3200;     // 16384
    int b = blockIdx.x, tid = threadIdx.x;
    for (int lin = tid; lin < V*C; lin += 256) xb_s[lin] = g_xbar[b*V*C + lin];

    const float* Wp[3] = {pw, tw, xw};
    const float* Bp[3] = {pb, tb, xb2};
    float* Op[3];
    Op[0] = g_phi; Op[1] = g_theta; Op[2] = g_Hbar;

    for (int w = 0; w < 3; w++) {
        for (int lin = tid; lin < C*K; lin += 256) W_s[lin] = Wp[w][lin];
        __syncthreads();
        for (int task = tid; task < V*(K/4); task += 256) {
            int v  = task >> 5;
            int k4 = (task & 31) << 2;
            float4 acc = *(const float4*)&Bp[w][k4];
            for (int c = 0; c < C; c++) {
                float a = xb_s[v*C + c];
                float4 wv = *(const float4*)&W_s[c*K + k4];
                acc.x += a*wv.x; acc.y += a*wv.y; acc.z += a*wv.z; acc.w += a*wv.w;
            }
            *(float4*)&Op[w][b*V*K + v*K + k4] = acc;
        }
        __syncthreads();
    }
}

// ---------------- K3: A_tilde[b][u][v][k] = A[k,u,v] + lam*(F@kappa + b) ----
#define PAIRS_PER_BLK 32
#define FPAD 132
__global__ void k3_atilde(const float* __restrict__ A, const float* __restrict__ lam_p,
                          const float* __restrict__ kw, const float* __restrict__ kb) {
    extern __shared__ float sm3[];
    float* kap_s = sm3;                 // 16384
    float* F_s   = sm3 + C*K;           // 32*132
    int b = blockIdx.x / 20;
    int chunk = blockIdx.x % 20;
    int tid = threadIdx.x;

    for (int lin = tid; lin < K*K; lin += 256) kap_s[lin] = kw[lin];

    for (int idx = tid; idx < PAIRS_PER_BLK*K; idx += 256) {
        int p = idx >> 7, m = idx & 127;
        int pair = chunk*PAIRS_PER_BLK + p;
        float f = 0.f;
        if (pair < V*V) {
            int i = pair / V, j = pair % V;
            f = tanhf(g_phi[(b*V+i)*K + m] - g_theta[(b*V+j)*K + m]);
        }
        F_s[p*FPAD + m] = f;
    }
    __syncthreads();

    int wid = tid >> 5, lane = tid & 31;
    int k0 = wid * 16;
    int pair = chunk*PAIRS_PER_BLK + lane;
    if (pair >= V*V) return;

    float acc[16];
#pragma unroll
    for (int q = 0; q < 16; q++) acc[q] = 0.f;

    for (int m = 0; m < K; m += 4) {
        float4 f4 = *(const float4*)&F_s[lane*FPAD + m];
#pragma unroll
        for (int g = 0; g < 4; g++) {
            float4 r0 = *(const float4*)&kap_s[(m+0)*K + k0 + g*4];
            float4 r1 = *(const float4*)&kap_s[(m+1)*K + k0 + g*4];
            float4 r2 = *(const float4*)&kap_s[(m+2)*K + k0 + g*4];
            float4 r3 = *(const float4*)&kap_s[(m+3)*K + k0 + g*4];
            acc[g*4+0] += f4.x*r0.x + f4.y*r1.x + f4.z*r2.x + f4.w*r3.x;
            acc[g*4+1] += f4.x*r0.y + f4.y*r1.y + f4.z*r2.y + f4.w*r3.y;
            acc[g*4+2] += f4.x*r0.z + f4.y*r1.z + f4.z*r2.z + f4.w*r3.z;
            acc[g*4+3] += f4.x*r0.w + f4.y*r1.w + f4.z*r2.w + f4.w*r3.w;
        }
    }

    float lamv = *lam_p;
    int i = pair / V, j = pair % V;
    int outbase = ((b*V + i)*V + j)*K + k0;
#pragma unroll
    for (int g = 0; g < 4; g++) {
        float4 r;
        int kk = k0 + g*4;
        r.x = A[((kk+0)*V + i)*V + j] + lamv*(acc[g*4+0] + kb[kk+0]);
        r.y = A[((kk+1)*V + i)*V + j] + lamv*(acc[g*4+1] + kb[kk+1]);
        r.z = A[((kk+2)*V + i)*V + j] + lamv*(acc[g*4+2] + kb[kk+2]);
        r.w = A[((kk+3)*V + i)*V + j] + lamv*(acc[g*4+3] + kb[kk+3]);
        *(float4*)&g_Atil[outbase + g*4] = r;
    }
}

// ---------------- K4: gate[b][k]  -------------------------------------------
__global__ void __launch_bounds__(512) k4_gate(
        const float* __restrict__ qw, const float* __restrict__ qb,
        const float* __restrict__ kw, const float* __restrict__ kb,
        const float* __restrict__ c1w, const float* __restrict__ c1b,
        const float* __restrict__ l1w, const float* __restrict__ l1b,
        const float* __restrict__ c2w, const float* __restrict__ c2b) {
    extern __shared__ float sm4[];
    float* Hb_s = sm4;                 // 3200
    float* Zb_s = Hb_s + 3200;         // 3200
    float* XQ_s = Zb_s + 3200;         // 3200
    float* XK_s = XQ_s + 3200;         // 3200
    float* qw_s = XK_s + 3200;         // 4096
    float* kw_s = qw_s + 4096;         // 4096
    float* ca_s = kw_s + 4096;         // 512
    float* c1_s = ca_s + 512;          // 32

    int b = blockIdx.x, tid = threadIdx.x;
    int k = tid & 127, uh = tid >> 7;
    for (int lin = tid; lin < V*K; lin += 512) Hb_s[lin] = g_Hbar[b*V*K + lin];
    __syncthreads();

    int u_lo = (uh == 0) ? 0 : (7 + 6*(uh-1));
    int nu   = (uh == 0) ? 7 : 6;

    for (int ui = 0; ui < nu; ui++) {
        int u = u_lo + ui;
        float acc = 0.f;
        const float* ap = g_Atil + ((size_t)(b*V + u)*V)*K + k;
#pragma unroll
        for (int v = 0; v < V; v++) acc += ap[v*K] * Hb_s[v*K + k];
        Zb_s[u*K + k] = acc;
    }
    __syncthreads();

    float accq[7], acck[7];
    for (int ui = 0; ui < nu; ui++) { accq[ui] = qb[k]; acck[ui] = kb[k]; }
    for (int mc = 0; mc < K; mc += 32) {
        for (int lin = tid; lin < 32*128; lin += 512) {
            int mm = lin >> 7, kk = lin & 127;
            qw_s[lin] = qw[(mc + mm)*K + kk];
            kw_s[lin] = kw[(mc + mm)*K + kk];
        }
        __syncthreads();
        for (int ui = 0; ui < nu; ui++) {
            int u = u_lo + ui;
            float aq = accq[ui], ak = acck[ui];
#pragma unroll
            for (int mm = 0; mm < 32; mm++) {
                float z = Zb_s[u*K + mc + mm];
                aq += z * qw_s[mm*128 + k];
                ak += z * kw_s[mm*128 + k];
            }
            accq[ui] = aq; acck[ui] = ak;
        }
        __syncthreads();
    }
    for (int ui = 0; ui < nu; ui++) {
        XQ_s[(u_lo+ui)*K + k] = accq[ui];
        XK_s[(u_lo+ui)*K + k] = acck[ui];
    }
    __syncthreads();

    const float inv_scale = 1.0f / sqrtf((float)T);
    float ca = 0.f;
    for (int ui = 0; ui < nu; ui++) {
        int u = u_lo + ui;
        float xq = XQ_s[u*K + k];
        float mx = -1e30f;
#pragma unroll
        for (int v = 0; v < V; v++) {
            float s = xq * XK_s[v*K + k] * inv_scale;
            mx = fmaxf(mx, s);
        }
        float den = 0.f, num = 0.f;
#pragma unroll
        for (int v = 0; v < V; v++) {
            float s = xq * XK_s[v*K + k] * inv_scale;
            float e = expf(s - mx);
            den += e;
            num += e * Hb_s[v*K + k];
        }
        ca += num / den;
    }
    ca_s[tid] = ca;
    __syncthreads();
    if (tid < 128)
        ca_s[tid] = (ca_s[tid] + ca_s[tid+128] + ca_s[tid+256] + ca_s[tid+384]) * (1.0f/V);
    __syncthreads();

    if (tid < R) {
        float t = c1b[tid];
        for (int kk = 0; kk < K; kk++) t += ca_s[kk] * c1w[kk*R + tid];
        float mu = t;
#pragma unroll
        for (int o = 16; o > 0; o >>= 1) mu += __shfl_xor_sync(0xffffffffu, mu, o);
        mu *= (1.0f/R);
        float d = t - mu;
        float var = d*d;
#pragma unroll
        for (int o = 16; o > 0; o >>= 1) var += __shfl_xor_sync(0xffffffffu, var, o);
        var *= (1.0f/R);
        float y = d * rsqrtf(var + 1e-5f) * l1w[tid] + l1b[tid];
        c1_s[tid] = 0.5f * y * (1.0f + erff(y * 0.70710678118654752f));
    }
    __syncthreads();

    if (tid < 128) {
        float g = c2b[k];
#pragma unroll
        for (int r = 0; r < R; r++) g += c1_s[r] * c2w[r*K + k];
        g_gate[b*K + k] = 1.0f / (1.0f + expf(-g));
    }
}

// ---------------- K5: H = x @ xi_w + b  (f32x2 GEMM, 128x128 tile) ----------
__global__ void __launch_bounds__(256, 2) k5_hgemm(const float* __restrict__ x,
                                                   const float* __restrict__ xiw,
                                                   const float* __restrict__ xib) {
    __shared__ float xs[16*256];   // [c][2r] -- each x scalar duplicated
    __shared__ float ws[16*128];   // [c][k]
    int tid = threadIdx.x;
    int tx = tid & 15, ty = tid >> 4;
    size_t row0 = (size_t)blockIdx.x * 128;

    unsigned long long acc[8][4];
#pragma unroll
    for (int i = 0; i < 8; i++)
#pragma unroll
        for (int j = 0; j < 4; j++) acc[i][j] = 0ull;

    for (int cc = 0; cc < C; cc += 16) {
        for (int lin = tid; lin < 2048; lin += 256) {
            int r = lin >> 4, c = lin & 15;
            float vx = x[(row0 + r)*C + cc + c];
            xs[c*256 + 2*r]     = vx;
            xs[c*256 + 2*r + 1] = vx;
        }
        for (int lin = tid; lin < 2048; lin += 256) {
            int c = lin >> 7, kk = lin & 127;
            ws[lin] = xiw[(cc + c)*K + kk];
        }
        __syncthreads();
#pragma unroll
        for (int c = 0; c < 16; c++) {
            // 8 dup-pairs (rows ty*8..ty*8+7) via 4x LDS.128 (broadcast groups)
            ulonglong2 a01 = *(const ulonglong2*)&xs[c*256 + ty*16];
            ulonglong2 a23 = *(const ulonglong2*)&xs[c*256 + ty*16 + 4];
            ulonglong2 a45 = *(const ulonglong2*)&xs[c*256 + ty*16 + 8];
            ulonglong2 a67 = *(const ulonglong2*)&xs[c*256 + ty*16 + 12];
            // 4 w-pairs (cols tx*8..tx*8+7) via 2x LDS.128
            ulonglong2 w01 = *(const ulonglong2*)&ws[c*128 + tx*8];
            ulonglong2 w23 = *(const ulonglong2*)&ws[c*128 + tx*8 + 4];
            unsigned long long av[8] = {a01.x, a01.y, a23.x, a23.y,
                                        a45.x, a45.y, a67.x, a67.y};
            unsigned long long wv[4] = {w01.x, w01.y, w23.x, w23.y};
#pragma unroll
            for (int i = 0; i < 8; i++) {
                acc[i][0] = fma2(av[i], wv[0], acc[i][0]);
                acc[i][1] = fma2(av[i], wv[1], acc[i][1]);
                acc[i][2] = fma2(av[i], wv[2], acc[i][2]);
                acc[i][3] = fma2(av[i], wv[3], acc[i][3]);
            }
        }
        __syncthreads();
    }

    float4 b0 = *(const float4*)&xib[tx*8];
    float4 b1 = *(const float4*)&xib[tx*8 + 4];
#pragma unroll
    for (int i = 0; i < 8; i++) {
        size_t row = row0 + ty*8 + i;
        float f0,f1,f2,f3,f4v,f5,f6,f7;
        unpack2(acc[i][0], f0, f1);
        unpack2(acc[i][1], f2, f3);
        unpack2(acc[i][2], f4v, f5);
        unpack2(acc[i][3], f6, f7);
        float4 o0, o1;
        o0.x = f0 + b0.x; o0.y = f1 + b0.y; o0.z = f2 + b0.z; o0.w = f3 + b0.w;
        o1.x = f4v + b1.x; o1.y = f5 + b1.y; o1.z = f6 + b1.z; o1.w = f7 + b1.w;
        *(float4*)&g_H[row*K + tx*8]     = o0;
        *(float4*)&g_H[row*K + tx*8 + 4] = o1;
    }
}

// ---------------- K6: Z_G = gate*(A_tilde . H) + LayerNorm (f32x2) ----------
#define TT 8
__global__ void __launch_bounds__(512, 1) k6_zg_ln(const float* __restrict__ l2w,
                                                   const float* __restrict__ l2b,
                                                   float* __restrict__ out) {
    extern __shared__ float sm6[];
    float* Hs   = sm6;                 // 200*128 = 25600
    float* As0  = Hs  + 25600;         // 3200
    float* As1  = As0 + 3200;          // 3200
    float* mu_s = As1 + 3200;          // 200
    float* rs_s = mu_s + 200;          // 200

    int b  = blockIdx.x >> 4;
    int tt = blockIdx.x & 15;
    int tid = threadIdx.x;
    int kp = tid & 63;                 // k-pair index (k = 2*kp, 2*kp+1)
    int tg = tid >> 6;                 // local t (0..7)

    const size_t base = ((size_t)(b*T + tt*TT))*V*K;

    for (int lin = tid; lin < TT*V*K; lin += 512)
        Hs[lin] = g_H[base + lin];

    const float* Ab = g_Atil + (size_t)b*V*V*K;
    for (int lin = tid; lin < V*K; lin += 512) {
        int u = lin >> 7, kk = lin & 127;
        As0[lin] = Ab[((size_t)u*V + 0)*K + kk];
    }
    __syncthreads();

    unsigned long long z[V];
#pragma unroll
    for (int u = 0; u < V; u++) z[u] = 0ull;

    for (int v = 0; v < V; v++) {
        float* cur = (v & 1) ? As1 : As0;
        float* nxt = (v & 1) ? As0 : As1;
        if (v + 1 < V) {
            for (int lin = tid; lin < V*K; lin += 512) {
                int u = lin >> 7, kk = lin & 127;
                nxt[lin] = Ab[((size_t)u*V + (v+1))*K + kk];
            }
        }
        unsigned long long h = *(const unsigned long long*)&Hs[(tg*V + v)*K + 2*kp];
#pragma unroll
        for (int u = 0; u < V; u++) {
            unsigned long long a = *(const unsigned long long*)&cur[u*K + 2*kp];
            z[u] = fma2(h, a, z[u]);
        }
        __syncthreads();
    }

    // gate and write Z back to Hs (H no longer needed)
    float2 gk = *(const float2*)&g_gate[b*K + 2*kp];
#pragma unroll
    for (int u = 0; u < V; u++) {
        float zl, zh;
        unpack2(z[u], zl, zh);
        Hs[(tg*V + u)*K + 2*kp]     = zl * gk.x;
        Hs[(tg*V + u)*K + 2*kp + 1] = zh * gk.y;
    }
    __syncthreads();

    // LayerNorm stats (rotated k-scan: conflict-free)
    for (int p = tid; p < TT*V; p += 512) {
        float s = 0.f, s2 = 0.f;
        for (int kk = 0; kk < K; kk++) {
            int k = (kk + p) & 127;
            float val = Hs[p*K + k];
            s += val; s2 += val*val;
        }
        float m = s * (1.0f/K);
        float var = s2 * (1.0f/K) - m*m;
        mu_s[p] = m;
        rs_s[p] = rsqrtf(var + 1e-5f);
    }
    __syncthreads();

    for (int lin = tid; lin < TT*V*K; lin += 512) {
        int r = lin >> 7, kk = lin & 127;
        float val = (Hs[lin] - mu_s[r]) * rs_s[r];
        out[base + lin] = val * l2w[kk] + l2b[kk];
    }
}

// ---------------- launch --------------------------------------------------
extern "C" void kernel_launch(void* const* d_in, const int* in_sizes, int n_in,
                              void* d_out, int out_size) {
    const float* x    = (const float*)d_in[0];
    const float* A    = (const float*)d_in[1];
    const float* lam  = (const float*)d_in[2];
    const float* phiw = (const float*)d_in[3];
    const float* phib = (const float*)d_in[4];
    const float* thw  = (const float*)d_in[5];
    const float* thb  = (const float*)d_in[6];
    const float* kapw = (const float*)d_in[7];
    const float* kapb = (const float*)d_in[8];
    const float* xiw  = (const float*)d_in[9];
    const float* xib  = (const float*)d_in[10];
    const float* qw   = (const float*)d_in[11];
    const float* qb   = (const float*)d_in[12];
    const float* kw   = (const float*)d_in[13];
    const float* kb   = (const float*)d_in[14];
    const float* c1w  = (const float*)d_in[15];
    const float* c1b  = (const float*)d_in[16];
    const float* l1w  = (const float*)d_in[17];
    const float* l1b  = (const float*)d_in[18];
    const float* c2w  = (const float*)d_in[19];
    const float* c2b  = (const float*)d_in[20];
    const float* l2w  = (const float*)d_in[21];
    const float* l2b  = (const float*)d_in[22];
    float* out = (float*)d_out;

    size_t sm2 = (size_t)(3200 + 16384) * 4;
    size_t sm3 = (size_t)(16384 + 32*FPAD) * 4;
    size_t sm4 = (size_t)(4*3200 + 2*4096 + 512 + 32) * 4;
    size_t sm6 = (size_t)(25600 + 3200 + 3200 + 200 + 200) * 4;

    cudaFuncSetAttribute(k2_small,  cudaFuncAttributeMaxDynamicSharedMemorySize, (int)sm2);
    cudaFuncSetAttribute(k3_atilde, cudaFuncAttributeMaxDynamicSharedMemorySize, (int)sm3);
    cudaFuncSetAttribute(k4_gate,   cudaFuncAttributeMaxDynamicSharedMemorySize, (int)sm4);
    cudaFuncSetAttribute(k6_zg_ln,  cudaFuncAttributeMaxDynamicSharedMemorySize, (int)sm6);

    k1_xbar<<<B*V, 128>>>(x);
    k2_small<<<B, 256, sm2>>>(phiw, phib, thw, thb, xiw, xib);
    k3_atilde<<<B*20, 256, sm3>>>(A, lam, kapw, kapb);
    k4_gate<<<B, 512, sm4>>>(qw, qb, kw, kb, c1w, c1b, l1w, l1b, c2w, c2b);
    k5_hgemm<<<(B*T*V)/128, 256>>>(x, xiw, xib);
    k6_zg_ln<<<B*16, 512, sm6>>>(l2w, l2b, out);
}

// round 9
// speedup vs baseline: 1.1004x; 1.1004x over previous
#include <cuda_runtime.h>
#include <math.h>

#define B 64
#define T 128
#define V 25
#define C 128
#define K 128
#define R 32

// ---------------- scratch (device globals; no allocations allowed) ----------
__device__ float g_xbar[B*V*C];
__device__ float g_phi [B*V*K];
__device__ float g_theta[B*V*K];
__device__ float g_Hbar[B*V*K];
__device__ float g_Atil[B*V*V*K];      // [b][u][v][k]
__device__ float g_gate[B*K];
__device__ float g_H[B*T*V*K];         // [b][t][v][k]

// ---------------- K1: xbar = mean_t x ---------------------------------------
__global__ void k1_xbar(const float* __restrict__ x) {
    int bv = blockIdx.x;
    int c  = threadIdx.x;
    int b = bv / V, v = bv % V;
    const float* p = x + ((size_t)(b*T)*V + v)*C + c;
    float acc = 0.f;
#pragma unroll 8
    for (int t = 0; t < T; t++) acc += p[(size_t)t*V*C];
    g_xbar[bv*C + c] = acc * (1.0f/T);
}

// ---------------- K2: phi_x / theta_x / Hbar --------------------------------
__global__ void k2_small(const float* __restrict__ pw, const float* __restrict__ pb,
                         const float* __restrict__ tw, const float* __restrict__ tb,
                         const float* __restrict__ xw, const float* __restrict__ xb2) {
    extern __shared__ float sm2[];
    float* xb_s = sm2;
    float* W_s  = sm2 + 3200;
    int b = blockIdx.x, tid = threadIdx.x;
    for (int lin = tid; lin < V*C; lin += 256) xb_s[lin] = g_xbar[b*V*C + lin];

    const float* Wp[3] = {pw, tw, xw};
    const float* Bp[3] = {pb, tb, xb2};
    float* Op[3];
    Op[0] = g_phi; Op[1] = g_theta; Op[2] = g_Hbar;

    for (int w = 0; w < 3; w++) {
        for (int lin = tid; lin < C*K; lin += 256) W_s[lin] = Wp[w][lin];
        __syncthreads();
        for (int task = tid; task < V*(K/4); task += 256) {
            int v  = task >> 5;
            int k4 = (task & 31) << 2;
            float4 acc = *(const float4*)&Bp[w][k4];
            for (int c = 0; c < C; c++) {
                float a = xb_s[v*C + c];
                float4 wv = *(const float4*)&W_s[c*K + k4];
                acc.x += a*wv.x; acc.y += a*wv.y; acc.z += a*wv.z; acc.w += a*wv.w;
            }
            *(float4*)&Op[w][b*V*K + v*K + k4] = acc;
        }
        __syncthreads();
    }
}

// ---------------- K3: A_tilde ----------------------------------------------
#define PAIRS_PER_BLK 32
#define FPAD 132
__global__ void k3_atilde(const float* __restrict__ A, const float* __restrict__ lam_p,
                          const float* __restrict__ kw, const float* __restrict__ kb) {
    extern __shared__ float sm3[];
    float* kap_s = sm3;
    float* F_s   = sm3 + C*K;
    int b = blockIdx.x / 20;
    int chunk = blockIdx.x % 20;
    int tid = threadIdx.x;

    for (int lin = tid; lin < K*K; lin += 256) kap_s[lin] = kw[lin];

    for (int idx = tid; idx < PAIRS_PER_BLK*K; idx += 256) {
        int p = idx >> 7, m = idx & 127;
        int pair = chunk*PAIRS_PER_BLK + p;
        float f = 0.f;
        if (pair < V*V) {
            int i = pair / V, j = pair % V;
            f = tanhf(g_phi[(b*V+i)*K + m] - g_theta[(b*V+j)*K + m]);
        }
        F_s[p*FPAD + m] = f;
    }
    __syncthreads();

    int wid = tid >> 5, lane = tid & 31;
    int k0 = wid * 16;
    int pair = chunk*PAIRS_PER_BLK + lane;
    if (pair >= V*V) return;

    float acc[16];
#pragma unroll
    for (int q = 0; q < 16; q++) acc[q] = 0.f;

    for (int m = 0; m < K; m += 4) {
        float4 f4 = *(const float4*)&F_s[lane*FPAD + m];
#pragma unroll
        for (int g = 0; g < 4; g++) {
            float4 r0 = *(const float4*)&kap_s[(m+0)*K + k0 + g*4];
            float4 r1 = *(const float4*)&kap_s[(m+1)*K + k0 + g*4];
            float4 r2 = *(const float4*)&kap_s[(m+2)*K + k0 + g*4];
            float4 r3 = *(const float4*)&kap_s[(m+3)*K + k0 + g*4];
            acc[g*4+0] += f4.x*r0.x + f4.y*r1.x + f4.z*r2.x + f4.w*r3.x;
            acc[g*4+1] += f4.x*r0.y + f4.y*r1.y + f4.z*r2.y + f4.w*r3.y;
            acc[g*4+2] += f4.x*r0.z + f4.y*r1.z + f4.z*r2.z + f4.w*r3.z;
            acc[g*4+3] += f4.x*r0.w + f4.y*r1.w + f4.z*r2.w + f4.w*r3.w;
        }
    }

    float lamv = *lam_p;
    int i = pair / V, j = pair % V;
    int outbase = ((b*V + i)*V + j)*K + k0;
#pragma unroll
    for (int g = 0; g < 4; g++) {
        float4 r;
        int kk = k0 + g*4;
        r.x = A[((kk+0)*V + i)*V + j] + lamv*(acc[g*4+0] + kb[kk+0]);
        r.y = A[((kk+1)*V + i)*V + j] + lamv*(acc[g*4+1] + kb[kk+1]);
        r.z = A[((kk+2)*V + i)*V + j] + lamv*(acc[g*4+2] + kb[kk+2]);
        r.w = A[((kk+3)*V + i)*V + j] + lamv*(acc[g*4+3] + kb[kk+3]);
        *(float4*)&g_Atil[outbase + g*4] = r;
    }
}

// ---------------- K4: gate[b][k] --------------------------------------------
__global__ void __launch_bounds__(512) k4_gate(
        const float* __restrict__ qw, const float* __restrict__ qb,
        const float* __restrict__ kw, const float* __restrict__ kb,
        const float* __restrict__ c1w, const float* __restrict__ c1b,
        const float* __restrict__ l1w, const float* __restrict__ l1b,
        const float* __restrict__ c2w, const float* __restrict__ c2b) {
    extern __shared__ float sm4[];
    float* Hb_s = sm4;
    float* Zb_s = Hb_s + 3200;
    float* XQ_s = Zb_s + 3200;
    float* XK_s = XQ_s + 3200;
    float* qw_s = XK_s + 3200;
    float* kw_s = qw_s + 4096;
    float* ca_s = kw_s + 4096;
    float* c1_s = ca_s + 512;

    int b = blockIdx.x, tid = threadIdx.x;
    int k = tid & 127, uh = tid >> 7;
    for (int lin = tid; lin < V*K; lin += 512) Hb_s[lin] = g_Hbar[b*V*K + lin];
    __syncthreads();

    int u_lo = (uh == 0) ? 0 : (7 + 6*(uh-1));
    int nu   = (uh == 0) ? 7 : 6;

    for (int ui = 0; ui < nu; ui++) {
        int u = u_lo + ui;
        float acc = 0.f;
        const float* ap = g_Atil + ((size_t)(b*V + u)*V)*K + k;
#pragma unroll
        for (int v = 0; v < V; v++) acc += ap[v*K] * Hb_s[v*K + k];
        Zb_s[u*K + k] = acc;
    }
    __syncthreads();

    float accq[7], acck[7];
    for (int ui = 0; ui < nu; ui++) { accq[ui] = qb[k]; acck[ui] = kb[k]; }
    for (int mc = 0; mc < K; mc += 32) {
        for (int lin = tid; lin < 32*128; lin += 512) {
            int mm = lin >> 7, kk = lin & 127;
            qw_s[lin] = qw[(mc + mm)*K + kk];
            kw_s[lin] = kw[(mc + mm)*K + kk];
        }
        __syncthreads();
        for (int ui = 0; ui < nu; ui++) {
            int u = u_lo + ui;
            float aq = accq[ui], ak = acck[ui];
#pragma unroll
            for (int mm = 0; mm < 32; mm++) {
                float z = Zb_s[u*K + mc + mm];
                aq += z * qw_s[mm*128 + k];
                ak += z * kw_s[mm*128 + k];
            }
            accq[ui] = aq; acck[ui] = ak;
        }
        __syncthreads();
    }
    for (int ui = 0; ui < nu; ui++) {
        XQ_s[(u_lo+ui)*K + k] = accq[ui];
        XK_s[(u_lo+ui)*K + k] = acck[ui];
    }
    __syncthreads();

    const float inv_scale = 1.0f / sqrtf((float)T);
    float ca = 0.f;
    for (int ui = 0; ui < nu; ui++) {
        int u = u_lo + ui;
        float xq = XQ_s[u*K + k];
        float mx = -1e30f;
#pragma unroll
        for (int v = 0; v < V; v++) {
            float s = xq * XK_s[v*K + k] * inv_scale;
            mx = fmaxf(mx, s);
        }
        float den = 0.f, num = 0.f;
#pragma unroll
        for (int v = 0; v < V; v++) {
            float s = xq * XK_s[v*K + k] * inv_scale;
            float e = expf(s - mx);
            den += e;
            num += e * Hb_s[v*K + k];
        }
        ca += num / den;
    }
    ca_s[tid] = ca;
    __syncthreads();
    if (tid < 128)
        ca_s[tid] = (ca_s[tid] + ca_s[tid+128] + ca_s[tid+256] + ca_s[tid+384]) * (1.0f/V);
    __syncthreads();

    if (tid < R) {
        float t = c1b[tid];
        for (int kk = 0; kk < K; kk++) t += ca_s[kk] * c1w[kk*R + tid];
        float mu = t;
#pragma unroll
        for (int o = 16; o > 0; o >>= 1) mu += __shfl_xor_sync(0xffffffffu, mu, o);
        mu *= (1.0f/R);
        float d = t - mu;
        float var = d*d;
#pragma unroll
        for (int o = 16; o > 0; o >>= 1) var += __shfl_xor_sync(0xffffffffu, var, o);
        var *= (1.0f/R);
        float y = d * rsqrtf(var + 1e-5f) * l1w[tid] + l1b[tid];
        c1_s[tid] = 0.5f * y * (1.0f + erff(y * 0.70710678118654752f));
    }
    __syncthreads();

    if (tid < 128) {
        float g = c2b[k];
#pragma unroll
        for (int r = 0; r < R; r++) g += c1_s[r] * c2w[r*K + k];
        g_gate[b*K + k] = 1.0f / (1.0f + expf(-g));
    }
}

// ---------------- K5: H = x @ xi_w + b  (plain fp32, 128x128 tile) ----------
__global__ void __launch_bounds__(256, 2) k5_hgemm(const float* __restrict__ x,
                                                   const float* __restrict__ xiw,
                                                   const float* __restrict__ xib) {
    __shared__ float xs[16*132];   // [c][r], padded
    __shared__ float bs[16*128];   // [c][k]
    int tid = threadIdx.x;
    int tx = tid & 15, ty = tid >> 4;
    size_t row0 = (size_t)blockIdx.x * 128;

    float acc[8][8];
#pragma unroll
    for (int i = 0; i < 8; i++)
#pragma unroll
        for (int j = 0; j < 8; j++) acc[i][j] = 0.f;

    for (int cc = 0; cc < C; cc += 16) {
#pragma unroll
        for (int rep = 0; rep < 8; rep++) {
            int lin = rep*256 + tid;
            int r = lin >> 4, c = lin & 15;
            xs[c*132 + r] = x[(row0 + r)*C + cc + c];
        }
#pragma unroll
        for (int rep = 0; rep < 8; rep++) {
            int lin = rep*256 + tid;
            int c = lin >> 7, kk = lin & 127;
            bs[c*128 + kk] = xiw[(cc + c)*K + kk];
        }
        __syncthreads();
#pragma unroll
        for (int c = 0; c < 16; c++) {
            float4 a0 = *(const float4*)&xs[c*132 + ty*8];
            float4 a1 = *(const float4*)&xs[c*132 + ty*8 + 4];
            float4 b0 = *(const float4*)&bs[c*128 + tx*8];
            float4 b1 = *(const float4*)&bs[c*128 + tx*8 + 4];
            float av[8] = {a0.x,a0.y,a0.z,a0.w,a1.x,a1.y,a1.z,a1.w};
            float bv[8] = {b0.x,b0.y,b0.z,b0.w,b1.x,b1.y,b1.z,b1.w};
#pragma unroll
            for (int i = 0; i < 8; i++)
#pragma unroll
                for (int j = 0; j < 8; j++) acc[i][j] += av[i]*bv[j];
        }
        __syncthreads();
    }

    float4 bb0 = *(const float4*)&xib[tx*8];
    float4 bb1 = *(const float4*)&xib[tx*8 + 4];
    float bias[8] = {bb0.x,bb0.y,bb0.z,bb0.w,bb1.x,bb1.y,bb1.z,bb1.w};
#pragma unroll
    for (int i = 0; i < 8; i++) {
        size_t row = row0 + ty*8 + i;
        float4 o0, o1;
        o0.x = acc[i][0]+bias[0]; o0.y = acc[i][1]+bias[1];
        o0.z = acc[i][2]+bias[2]; o0.w = acc[i][3]+bias[3];
        o1.x = acc[i][4]+bias[4]; o1.y = acc[i][5]+bias[5];
        o1.z = acc[i][6]+bias[6]; o1.w = acc[i][7]+bias[7];
        *(float4*)&g_H[row*K + tx*8]     = o0;
        *(float4*)&g_H[row*K + tx*8 + 4] = o1;
    }
}

// ---------------- K6: Z_G = gate*(A_tilde . H) + LayerNorm (plain fp32) -----
#define TT 8
__global__ void __launch_bounds__(512, 1) k6_zg_ln(const float* __restrict__ l2w,
                                                   const float* __restrict__ l2b,
                                                   float* __restrict__ out) {
    extern __shared__ float sm6[];
    float* Hs   = sm6;                 // 200*128 = 25600
    float* As0  = Hs  + 25600;         // 3200
    float* As1  = As0 + 3200;          // 3200
    float* mu_s = As1 + 3200;          // 200
    float* rs_s = mu_s + 200;          // 200

    int b  = blockIdx.x >> 4;
    int tt = blockIdx.x & 15;
    int tid = threadIdx.x;
    int kp = tid & 63;                 // k-pair index (k = 2*kp, 2*kp+1)
    int tg = tid >> 6;                 // local t (0..7)

    const size_t base = ((size_t)(b*T + tt*TT))*V*K;

    for (int lin = tid; lin < TT*V*K; lin += 512)
        Hs[lin] = g_H[base + lin];

    const float* Ab = g_Atil + (size_t)b*V*V*K;
    for (int lin = tid; lin < V*K; lin += 512) {
        int u = lin >> 7, kk = lin & 127;
        As0[lin] = Ab[((size_t)u*V + 0)*K + kk];
    }
    __syncthreads();

    float2 z[V];
#pragma unroll
    for (int u = 0; u < V; u++) { z[u].x = 0.f; z[u].y = 0.f; }

    for (int v = 0; v < V; v++) {
        float* cur = (v & 1) ? As1 : As0;
        float* nxt = (v & 1) ? As0 : As1;
        if (v + 1 < V) {
            for (int lin = tid; lin < V*K; lin += 512) {
                int u = lin >> 7, kk = lin & 127;
                nxt[lin] = Ab[((size_t)u*V + (v+1))*K + kk];
            }
        }
        float2 h = *(const float2*)&Hs[(tg*V + v)*K + 2*kp];
#pragma unroll
        for (int u = 0; u < V; u++) {
            float2 a = *(const float2*)&cur[u*K + 2*kp];
            z[u].x += h.x * a.x;
            z[u].y += h.y * a.y;
        }
        __syncthreads();
    }

    float2 gk = *(const float2*)&g_gate[b*K + 2*kp];
#pragma unroll
    for (int u = 0; u < V; u++) {
        Hs[(tg*V + u)*K + 2*kp]     = z[u].x * gk.x;
        Hs[(tg*V + u)*K + 2*kp + 1] = z[u].y * gk.y;
    }
    __syncthreads();

    for (int p = tid; p < TT*V; p += 512) {
        float s = 0.f, s2 = 0.f;
        for (int kk = 0; kk < K; kk++) {
            int k = (kk + p) & 127;
            float val = Hs[p*K + k];
            s += val; s2 += val*val;
        }
        float m = s * (1.0f/K);
        float var = s2 * (1.0f/K) - m*m;
        mu_s[p] = m;
        rs_s[p] = rsqrtf(var + 1e-5f);
    }
    __syncthreads();

    for (int lin = tid; lin < TT*V*K; lin += 512) {
        int r = lin >> 7, kk = lin & 127;
        float val = (Hs[lin] - mu_s[r]) * rs_s[r];
        out[base + lin] = val * l2w[kk] + l2b[kk];
    }
}

// ---------------- launch ----------------------------------------------------
extern "C" void kernel_launch(void* const* d_in, const int* in_sizes, int n_in,
                              void* d_out, int out_size) {
    const float* x    = (const float*)d_in[0];
    const float* A    = (const float*)d_in[1];
    const float* lam  = (const float*)d_in[2];
    const float* phiw = (const float*)d_in[3];
    const float* phib = (const float*)d_in[4];
    const float* thw  = (const float*)d_in[5];
    const float* thb  = (const float*)d_in[6];
    const float* kapw = (const float*)d_in[7];
    const float* kapb = (const float*)d_in[8];
    const float* xiw  = (const float*)d_in[9];
    const float* xib  = (const float*)d_in[10];
    const float* qw   = (const float*)d_in[11];
    const float* qb   = (const float*)d_in[12];
    const float* kw   = (const float*)d_in[13];
    const float* kb   = (const float*)d_in[14];
    const float* c1w  = (const float*)d_in[15];
    const float* c1b  = (const float*)d_in[16];
    const float* l1w  = (const float*)d_in[17];
    const float* l1b  = (const float*)d_in[18];
    const float* c2w  = (const float*)d_in[19];
    const float* c2b  = (const float*)d_in[20];
    const float* l2w  = (const float*)d_in[21];
    const float* l2b  = (const float*)d_in[22];
    float* out = (float*)d_out;

    size_t sm2 = (size_t)(3200 + 16384) * 4;
    size_t sm3 = (size_t)(16384 + 32*FPAD) * 4;
    size_t sm4 = (size_t)(4*3200 + 2*4096 + 512 + 32) * 4;
    size_t sm6 = (size_t)(25600 + 3200 + 3200 + 200 + 200) * 4;

    cudaFuncSetAttribute(k2_small,  cudaFuncAttributeMaxDynamicSharedMemorySize, (int)sm2);
    cudaFuncSetAttribute(k3_atilde, cudaFuncAttributeMaxDynamicSharedMemorySize, (int)sm3);
    cudaFuncSetAttribute(k4_gate,   cudaFuncAttributeMaxDynamicSharedMemorySize, (int)sm4);
    cudaFuncSetAttribute(k6_zg_ln,  cudaFuncAttributeMaxDynamicSharedMemorySize, (int)sm6);

    k1_xbar<<<B*V, 128>>>(x);
    k2_small<<<B, 256, sm2>>>(phiw, phib, thw, thb, xiw, xib);
    k3_atilde<<<B*20, 256, sm3>>>(A, lam, kapw, kapb);
    k4_gate<<<B, 512, sm4>>>(qw, qb, kw, kb, c1w, c1b, l1w, l1b, c2w, c2b);
    k5_hgemm<<<(B*T*V)/128, 256>>>(x, xiw, xib);
    k6_zg_ln<<<B*16, 512, sm6>>>(l2w, l2b, out);
}

// round 10
// speedup vs baseline: 1.1359x; 1.0323x over previous
#include <cuda_runtime.h>
#include <math.h>

#define B 64
#define T 128
#define V 25
#define C 128
#define K 128
#define R 32

// ---------------- scratch (device globals; no allocations allowed) ----------
__device__ float g_xbar[B*V*C];
__device__ float g_phi [B*V*K];
__device__ float g_theta[B*V*K];
__device__ float g_Hbar[B*V*K];
__device__ float g_Atil[B*V*V*K];      // [b][u][v][k]
__device__ float g_gate[B*K];

// ---------------- K1: xbar = mean_t x ---------------------------------------
__global__ void k1_xbar(const float* __restrict__ x) {
    int bv = blockIdx.x;
    int c  = threadIdx.x;
    int b = bv / V, v = bv % V;
    const float* p = x + ((size_t)(b*T)*V + v)*C + c;
    float acc = 0.f;
#pragma unroll 8
    for (int t = 0; t < T; t++) acc += p[(size_t)t*V*C];
    g_xbar[bv*C + c] = acc * (1.0f/T);
}

// ---------------- K2: phi_x / theta_x / Hbar --------------------------------
__global__ void k2_small(const float* __restrict__ pw, const float* __restrict__ pb,
                         const float* __restrict__ tw, const float* __restrict__ tb,
                         const float* __restrict__ xw, const float* __restrict__ xb2) {
    extern __shared__ float sm2[];
    float* xb_s = sm2;
    float* W_s  = sm2 + 3200;
    int b = blockIdx.x, tid = threadIdx.x;
    for (int lin = tid; lin < V*C; lin += 256) xb_s[lin] = g_xbar[b*V*C + lin];

    const float* Wp[3] = {pw, tw, xw};
    const float* Bp[3] = {pb, tb, xb2};
    float* Op[3];
    Op[0] = g_phi; Op[1] = g_theta; Op[2] = g_Hbar;

    for (int w = 0; w < 3; w++) {
        for (int lin = tid; lin < C*K; lin += 256) W_s[lin] = Wp[w][lin];
        __syncthreads();
        for (int task = tid; task < V*(K/4); task += 256) {
            int v  = task >> 5;
            int k4 = (task & 31) << 2;
            float4 acc = *(const float4*)&Bp[w][k4];
            for (int c = 0; c < C; c++) {
                float a = xb_s[v*C + c];
                float4 wv = *(const float4*)&W_s[c*K + k4];
                acc.x += a*wv.x; acc.y += a*wv.y; acc.z += a*wv.z; acc.w += a*wv.w;
            }
            *(float4*)&Op[w][b*V*K + v*K + k4] = acc;
        }
        __syncthreads();
    }
}

// ---------------- K3: A_tilde ----------------------------------------------
#define PAIRS_PER_BLK 32
#define FPAD 132
__global__ void k3_atilde(const float* __restrict__ A, const float* __restrict__ lam_p,
                          const float* __restrict__ kw, const float* __restrict__ kb) {
    extern __shared__ float sm3[];
    float* kap_s = sm3;
    float* F_s   = sm3 + C*K;
    int b = blockIdx.x / 20;
    int chunk = blockIdx.x % 20;
    int tid = threadIdx.x;

    for (int lin = tid; lin < K*K; lin += 256) kap_s[lin] = kw[lin];

    for (int idx = tid; idx < PAIRS_PER_BLK*K; idx += 256) {
        int p = idx >> 7, m = idx & 127;
        int pair = chunk*PAIRS_PER_BLK + p;
        float f = 0.f;
        if (pair < V*V) {
            int i = pair / V, j = pair % V;
            f = tanhf(g_phi[(b*V+i)*K + m] - g_theta[(b*V+j)*K + m]);
        }
        F_s[p*FPAD + m] = f;
    }
    __syncthreads();

    int wid = tid >> 5, lane = tid & 31;
    int k0 = wid * 16;
    int pair = chunk*PAIRS_PER_BLK + lane;
    if (pair >= V*V) return;

    float acc[16];
#pragma unroll
    for (int q = 0; q < 16; q++) acc[q] = 0.f;

    for (int m = 0; m < K; m += 4) {
        float4 f4 = *(const float4*)&F_s[lane*FPAD + m];
#pragma unroll
        for (int g = 0; g < 4; g++) {
            float4 r0 = *(const float4*)&kap_s[(m+0)*K + k0 + g*4];
            float4 r1 = *(const float4*)&kap_s[(m+1)*K + k0 + g*4];
            float4 r2 = *(const float4*)&kap_s[(m+2)*K + k0 + g*4];
            float4 r3 = *(const float4*)&kap_s[(m+3)*K + k0 + g*4];
            acc[g*4+0] += f4.x*r0.x + f4.y*r1.x + f4.z*r2.x + f4.w*r3.x;
            acc[g*4+1] += f4.x*r0.y + f4.y*r1.y + f4.z*r2.y + f4.w*r3.y;
            acc[g*4+2] += f4.x*r0.z + f4.y*r1.z + f4.z*r2.z + f4.w*r3.z;
            acc[g*4+3] += f4.x*r0.w + f4.y*r1.w + f4.z*r2.w + f4.w*r3.w;
        }
    }

    float lamv = *lam_p;
    int i = pair / V, j = pair % V;
    int outbase = ((b*V + i)*V + j)*K + k0;
#pragma unroll
    for (int g = 0; g < 4; g++) {
        float4 r;
        int kk = k0 + g*4;
        r.x = A[((kk+0)*V + i)*V + j] + lamv*(acc[g*4+0] + kb[kk+0]);
        r.y = A[((kk+1)*V + i)*V + j] + lamv*(acc[g*4+1] + kb[kk+1]);
        r.z = A[((kk+2)*V + i)*V + j] + lamv*(acc[g*4+2] + kb[kk+2]);
        r.w = A[((kk+3)*V + i)*V + j] + lamv*(acc[g*4+3] + kb[kk+3]);
        *(float4*)&g_Atil[outbase + g*4] = r;
    }
}

// ---------------- K4: gate[b][k] --------------------------------------------
__global__ void __launch_bounds__(512) k4_gate(
        const float* __restrict__ qw, const float* __restrict__ qb,
        const float* __restrict__ kw, const float* __restrict__ kb,
        const float* __restrict__ c1w, const float* __restrict__ c1b,
        const float* __restrict__ l1w, const float* __restrict__ l1b,
        const float* __restrict__ c2w, const float* __restrict__ c2b) {
    extern __shared__ float sm4[];
    float* Hb_s = sm4;
    float* Zb_s = Hb_s + 3200;
    float* XQ_s = Zb_s + 3200;
    float* XK_s = XQ_s + 3200;
    float* qw_s = XK_s + 3200;
    float* kw_s = qw_s + 4096;
    float* ca_s = kw_s + 4096;
    float* c1_s = ca_s + 512;

    int b = blockIdx.x, tid = threadIdx.x;
    int k = tid & 127, uh = tid >> 7;
    for (int lin = tid; lin < V*K; lin += 512) Hb_s[lin] = g_Hbar[b*V*K + lin];
    __syncthreads();

    int u_lo = (uh == 0) ? 0 : (7 + 6*(uh-1));
    int nu   = (uh == 0) ? 7 : 6;

    for (int ui = 0; ui < nu; ui++) {
        int u = u_lo + ui;
        float acc = 0.f;
        const float* ap = g_Atil + ((size_t)(b*V + u)*V)*K + k;
#pragma unroll
        for (int v = 0; v < V; v++) acc += ap[v*K] * Hb_s[v*K + k];
        Zb_s[u*K + k] = acc;
    }
    __syncthreads();

    float accq[7], acck[7];
    for (int ui = 0; ui < nu; ui++) { accq[ui] = qb[k]; acck[ui] = kb[k]; }
    for (int mc = 0; mc < K; mc += 32) {
        for (int lin = tid; lin < 32*128; lin += 512) {
            int mm = lin >> 7, kk = lin & 127;
            qw_s[lin] = qw[(mc + mm)*K + kk];
            kw_s[lin] = kw[(mc + mm)*K + kk];
        }
        __syncthreads();
        for (int ui = 0; ui < nu; ui++) {
            int u = u_lo + ui;
            float aq = accq[ui], ak = acck[ui];
#pragma unroll
            for (int mm = 0; mm < 32; mm++) {
                float z = Zb_s[u*K + mc + mm];
                aq += z * qw_s[mm*128 + k];
                ak += z * kw_s[mm*128 + k];
            }
            accq[ui] = aq; acck[ui] = ak;
        }
        __syncthreads();
    }
    for (int ui = 0; ui < nu; ui++) {
        XQ_s[(u_lo+ui)*K + k] = accq[ui];
        XK_s[(u_lo+ui)*K + k] = acck[ui];
    }
    __syncthreads();

    const float inv_scale = 1.0f / sqrtf((float)T);
    float ca = 0.f;
    for (int ui = 0; ui < nu; ui++) {
        int u = u_lo + ui;
        float xq = XQ_s[u*K + k];
        float mx = -1e30f;
#pragma unroll
        for (int v = 0; v < V; v++) {
            float s = xq * XK_s[v*K + k] * inv_scale;
            mx = fmaxf(mx, s);
        }
        float den = 0.f, num = 0.f;
#pragma unroll
        for (int v = 0; v < V; v++) {
            float s = xq * XK_s[v*K + k] * inv_scale;
            float e = expf(s - mx);
            den += e;
            num += e * Hb_s[v*K + k];
        }
        ca += num / den;
    }
    ca_s[tid] = ca;
    __syncthreads();
    if (tid < 128)
        ca_s[tid] = (ca_s[tid] + ca_s[tid+128] + ca_s[tid+256] + ca_s[tid+384]) * (1.0f/V);
    __syncthreads();

    if (tid < R) {
        float t = c1b[tid];
        for (int kk = 0; kk < K; kk++) t += ca_s[kk] * c1w[kk*R + tid];
        float mu = t;
#pragma unroll
        for (int o = 16; o > 0; o >>= 1) mu += __shfl_xor_sync(0xffffffffu, mu, o);
        mu *= (1.0f/R);
        float d = t - mu;
        float var = d*d;
#pragma unroll
        for (int o = 16; o > 0; o >>= 1) var += __shfl_xor_sync(0xffffffffu, var, o);
        var *= (1.0f/R);
        float y = d * rsqrtf(var + 1e-5f) * l1w[tid] + l1b[tid];
        c1_s[tid] = 0.5f * y * (1.0f + erff(y * 0.70710678118654752f));
    }
    __syncthreads();

    if (tid < 128) {
        float g = c2b[k];
#pragma unroll
        for (int r = 0; r < R; r++) g += c1_s[r] * c2w[r*K + k];
        g_gate[b*K + k] = 1.0f / (1.0f + expf(-g));
    }
}

// ---------------- K56: fused H-GEMM (plain fp32) + gated GCN + LayerNorm ----
// 512 threads. Phase A: warp w -> (t = w>>1, k-half = w&1); per-thread
// acc[25][2] (50 regs). Phase B: r9-k6 structure (kp = tid&63, tg = tid>>6,
// z[25] float2, double-buffered A_tilde staging). 1024 blocks.
#define TT 8
__global__ void __launch_bounds__(512, 1) k56_fused(
        const float* __restrict__ x,
        const float* __restrict__ xiw, const float* __restrict__ xib,
        const float* __restrict__ l2w, const float* __restrict__ l2b,
        float* __restrict__ out) {
    extern __shared__ float sm6[];
    float* Hs   = sm6;                 // 200*128 = 25600
    float* xs   = Hs  + 25600;         // 200*16  = 3200
    float* ws   = xs  + 3200;          // 16*128  = 2048
    float* As0  = ws  + 2048;          // 3200
    float* As1  = As0 + 3200;          // 3200
    float* mu_s = As1 + 3200;          // 200
    float* rs_s = mu_s + 200;          // 200

    int b  = blockIdx.x >> 4;
    int tt = blockIdx.x & 15;
    int tid  = threadIdx.x;
    int wid  = tid >> 5, lane = tid & 31;

    // ---------- Phase A: H tile [200 x 128] = x_tile @ xi_w + bias ----------
    int ta = wid >> 1;                 // t-row group 0..7
    int kh = wid & 1;                  // k half 0..1
    int kc = kh*64 + lane*2;           // 2 cols per thread

    const size_t xbase = ((size_t)(b*T + tt*TT))*V*C;  // 200 contiguous rows

    float2 acc[V];
#pragma unroll
    for (int v = 0; v < V; v++) { acc[v].x = 0.f; acc[v].y = 0.f; }

    for (int cc = 0; cc < C; cc += 16) {
        // stage x chunk [200 rows x 16 c]
        for (int lin = tid; lin < 200*16; lin += 512) {
            int r = lin >> 4, c = lin & 15;
            xs[lin] = x[xbase + (size_t)r*C + cc + c];
        }
        // stage w chunk [16 c x 128 k] (vectorized)
        for (int lin = tid; lin < 512; lin += 512) {
            int c = lin >> 5, k4 = (lin & 31) << 2;
            *(float4*)&ws[c*128 + k4] = *(const float4*)&xiw[(cc + c)*K + k4];
        }
        __syncthreads();
#pragma unroll
        for (int c = 0; c < 16; c++) {
            float2 w2 = *(const float2*)&ws[c*128 + kc];
            const float* xr = &xs[(ta*V)*16 + c];
#pragma unroll
            for (int v = 0; v < V; v++) {
                float xv = xr[v*16];           // warp-broadcast
                acc[v].x += xv * w2.x;
                acc[v].y += xv * w2.y;
            }
        }
        __syncthreads();
    }

    // write H tile (+bias) to smem
    {
        float2 bias2 = *(const float2*)&xib[kc];
#pragma unroll
        for (int v = 0; v < V; v++) {
            float2 o;
            o.x = acc[v].x + bias2.x;
            o.y = acc[v].y + bias2.y;
            *(float2*)&Hs[(ta*V + v)*K + kc] = o;
        }
    }
    __syncthreads();

    // ---------- Phase B: Z = gate * (A_tilde . H), LayerNorm over k ----------
    int kp = tid & 63;                 // k-pair index (k = 2*kp, 2*kp+1)
    int tg = tid >> 6;                 // local t (0..7)

    const float* Ab = g_Atil + (size_t)b*V*V*K;
    for (int lin = tid; lin < V*K; lin += 512) {
        int u = lin >> 7, kk = lin & 127;
        As0[lin] = Ab[((size_t)u*V + 0)*K + kk];
    }
    __syncthreads();

    float2 z[V];
#pragma unroll
    for (int u = 0; u < V; u++) { z[u].x = 0.f; z[u].y = 0.f; }

    for (int v = 0; v < V; v++) {
        float* cur = (v & 1) ? As1 : As0;
        float* nxt = (v & 1) ? As0 : As1;
        if (v + 1 < V) {
            for (int lin = tid; lin < V*K; lin += 512) {
                int u = lin >> 7, kk = lin & 127;
                nxt[lin] = Ab[((size_t)u*V + (v+1))*K + kk];
            }
        }
        float2 h = *(const float2*)&Hs[(tg*V + v)*K + 2*kp];
#pragma unroll
        for (int u = 0; u < V; u++) {
            float2 a = *(const float2*)&cur[u*K + 2*kp];
            z[u].x += h.x * a.x;
            z[u].y += h.y * a.y;
        }
        __syncthreads();
    }

    float2 gk = *(const float2*)&g_gate[b*K + 2*kp];
#pragma unroll
    for (int u = 0; u < V; u++) {
        Hs[(tg*V + u)*K + 2*kp]     = z[u].x * gk.x;
        Hs[(tg*V + u)*K + 2*kp + 1] = z[u].y * gk.y;
    }
    __syncthreads();

    for (int p = tid; p < TT*V; p += 512) {
        float s = 0.f, s2 = 0.f;
        for (int kk = 0; kk < K; kk++) {
            int k = (kk + p) & 127;
            float val = Hs[p*K + k];
            s += val; s2 += val*val;
        }
        float m = s * (1.0f/K);
        float var = s2 * (1.0f/K) - m*m;
        mu_s[p] = m;
        rs_s[p] = rsqrtf(var + 1e-5f);
    }
    __syncthreads();

    const size_t obase = ((size_t)(b*T + tt*TT))*V*K;
    for (int lin = tid; lin < TT*V*K; lin += 512) {
        int r = lin >> 7, kk = lin & 127;
        float val = (Hs[lin] - mu_s[r]) * rs_s[r];
        out[obase + lin] = val * l2w[kk] + l2b[kk];
    }
}

// ---------------- launch ----------------------------------------------------
extern "C" void kernel_launch(void* const* d_in, const int* in_sizes, int n_in,
                              void* d_out, int out_size) {
    const float* x    = (const float*)d_in[0];
    const float* A    = (const float*)d_in[1];
    const float* lam  = (const float*)d_in[2];
    const float* phiw = (const float*)d_in[3];
    const float* phib = (const float*)d_in[4];
    const float* thw  = (const float*)d_in[5];
    const float* thb  = (const float*)d_in[6];
    const float* kapw = (const float*)d_in[7];
    const float* kapb = (const float*)d_in[8];
    const float* xiw  = (const float*)d_in[9];
    const float* xib  = (const float*)d_in[10];
    const float* qw   = (const float*)d_in[11];
    const float* qb   = (const float*)d_in[12];
    const float* kw   = (const float*)d_in[13];
    const float* kb   = (const float*)d_in[14];
    const float* c1w  = (const float*)d_in[15];
    const float* c1b  = (const float*)d_in[16];
    const float* l1w  = (const float*)d_in[17];
    const float* l1b  = (const float*)d_in[18];
    const float* c2w  = (const float*)d_in[19];
    const float* c2b  = (const float*)d_in[20];
    const float* l2w  = (const float*)d_in[21];
    const float* l2b  = (const float*)d_in[22];
    float* out = (float*)d_out;

    size_t sm2  = (size_t)(3200 + 16384) * 4;
    size_t sm3  = (size_t)(16384 + 32*FPAD) * 4;
    size_t sm4  = (size_t)(4*3200 + 2*4096 + 512 + 32) * 4;
    size_t sm56 = (size_t)(25600 + 3200 + 2048 + 3200 + 3200 + 200 + 200) * 4;

    cudaFuncSetAttribute(k2_small,  cudaFuncAttributeMaxDynamicSharedMemorySize, (int)sm2);
    cudaFuncSetAttribute(k3_atilde, cudaFuncAttributeMaxDynamicSharedMemorySize, (int)sm3);
    cudaFuncSetAttribute(k4_gate,   cudaFuncAttributeMaxDynamicSharedMemorySize, (int)sm4);
    cudaFuncSetAttribute(k56_fused, cudaFuncAttributeMaxDynamicSharedMemorySize, (int)sm56);

    k1_xbar<<<B*V, 128>>>(x);
    k2_small<<<B, 256, sm2>>>(phiw, phib, thw, thb, xiw, xib);
    k3_atilde<<<B*20, 256, sm3>>>(A, lam, kapw, kapb);
    k4_gate<<<B, 512, sm4>>>(qw, qb, kw, kb, c1w, c1b, l1w, l1b, c2w, c2b);
    k56_fused<<<B*16, 512, sm56>>>(x, xiw, xib, l2w, l2b, out);
}

// round 11
// speedup vs baseline: 1.4420x; 1.2695x over previous
#include <cuda_runtime.h>
#include <math.h>

#define B 64
#define T 128
#define V 25
#define C 128
#define K 128
#define R 32

// ---------------- scratch (device globals; no allocations allowed) ----------
__device__ float g_xbar[B*V*C];
__device__ float g_phi [B*V*K];
__device__ float g_theta[B*V*K];
__device__ float g_Hbar[B*V*K];
__device__ float g_Atil[B*V*V*K];      // [b][u][v][k]
__device__ float g_gate[B*K];

// f32x2 packed FMA (SASS FFMA2) -- exact fp32, 2x FFMA-pipe rate
__device__ __forceinline__ unsigned long long fma2(unsigned long long a,
                                                   unsigned long long b,
                                                   unsigned long long c) {
    unsigned long long d;
    asm("fma.rn.f32x2 %0, %1, %2, %3;" : "=l"(d) : "l"(a), "l"(b), "l"(c));
    return d;
}
__device__ __forceinline__ void unpack2(unsigned long long p, float& lo, float& hi) {
    asm("mov.b64 {%0,%1}, %2;" : "=f"(lo), "=f"(hi) : "l"(p));
}

// ---------------- K1: xbar = mean_t x ---------------------------------------
__global__ void k1_xbar(const float* __restrict__ x) {
    int bv = blockIdx.x;
    int c  = threadIdx.x;
    int b = bv / V, v = bv % V;
    const float* p = x + ((size_t)(b*T)*V + v)*C + c;
    float acc = 0.f;
#pragma unroll 8
    for (int t = 0; t < T; t++) acc += p[(size_t)t*V*C];
    g_xbar[bv*C + c] = acc * (1.0f/T);
}

// ---------------- K2: phi_x / theta_x / Hbar --------------------------------
__global__ void k2_small(const float* __restrict__ pw, const float* __restrict__ pb,
                         const float* __restrict__ tw, const float* __restrict__ tb,
                         const float* __restrict__ xw, const float* __restrict__ xb2) {
    extern __shared__ float sm2[];
    float* xb_s = sm2;
    float* W_s  = sm2 + 3200;
    int b = blockIdx.x, tid = threadIdx.x;
    for (int lin = tid; lin < V*C; lin += 256) xb_s[lin] = g_xbar[b*V*C + lin];

    const float* Wp[3] = {pw, tw, xw};
    const float* Bp[3] = {pb, tb, xb2};
    float* Op[3];
    Op[0] = g_phi; Op[1] = g_theta; Op[2] = g_Hbar;

    for (int w = 0; w < 3; w++) {
        for (int lin = tid; lin < C*K; lin += 256) W_s[lin] = Wp[w][lin];
        __syncthreads();
        for (int task = tid; task < V*(K/4); task += 256) {
            int v  = task >> 5;
            int k4 = (task & 31) << 2;
            float4 acc = *(const float4*)&Bp[w][k4];
            for (int c = 0; c < C; c++) {
                float a = xb_s[v*C + c];
                float4 wv = *(const float4*)&W_s[c*K + k4];
                acc.x += a*wv.x; acc.y += a*wv.y; acc.z += a*wv.z; acc.w += a*wv.w;
            }
            *(float4*)&Op[w][b*V*K + v*K + k4] = acc;
        }
        __syncthreads();
    }
}

// ---------------- K3: A_tilde ----------------------------------------------
#define PAIRS_PER_BLK 32
#define FPAD 132
__global__ void k3_atilde(const float* __restrict__ A, const float* __restrict__ lam_p,
                          const float* __restrict__ kw, const float* __restrict__ kb) {
    extern __shared__ float sm3[];
    float* kap_s = sm3;
    float* F_s   = sm3 + C*K;
    int b = blockIdx.x / 20;
    int chunk = blockIdx.x % 20;
    int tid = threadIdx.x;

    for (int lin = tid; lin < K*K; lin += 256) kap_s[lin] = kw[lin];

    for (int idx = tid; idx < PAIRS_PER_BLK*K; idx += 256) {
        int p = idx >> 7, m = idx & 127;
        int pair = chunk*PAIRS_PER_BLK + p;
        float f = 0.f;
        if (pair < V*V) {
            int i = pair / V, j = pair % V;
            f = tanhf(g_phi[(b*V+i)*K + m] - g_theta[(b*V+j)*K + m]);
        }
        F_s[p*FPAD + m] = f;
    }
    __syncthreads();

    int wid = tid >> 5, lane = tid & 31;
    int k0 = wid * 16;
    int pair = chunk*PAIRS_PER_BLK + lane;
    if (pair >= V*V) return;

    float acc[16];
#pragma unroll
    for (int q = 0; q < 16; q++) acc[q] = 0.f;

    for (int m = 0; m < K; m += 4) {
        float4 f4 = *(const float4*)&F_s[lane*FPAD + m];
#pragma unroll
        for (int g = 0; g < 4; g++) {
            float4 r0 = *(const float4*)&kap_s[(m+0)*K + k0 + g*4];
            float4 r1 = *(const float4*)&kap_s[(m+1)*K + k0 + g*4];
            float4 r2 = *(const float4*)&kap_s[(m+2)*K + k0 + g*4];
            float4 r3 = *(const float4*)&kap_s[(m+3)*K + k0 + g*4];
            acc[g*4+0] += f4.x*r0.x + f4.y*r1.x + f4.z*r2.x + f4.w*r3.x;
            acc[g*4+1] += f4.x*r0.y + f4.y*r1.y + f4.z*r2.y + f4.w*r3.y;
            acc[g*4+2] += f4.x*r0.z + f4.y*r1.z + f4.z*r2.z + f4.w*r3.z;
            acc[g*4+3] += f4.x*r0.w + f4.y*r1.w + f4.z*r2.w + f4.w*r3.w;
        }
    }

    float lamv = *lam_p;
    int i = pair / V, j = pair % V;
    int outbase = ((b*V + i)*V + j)*K + k0;
#pragma unroll
    for (int g = 0; g < 4; g++) {
        float4 r;
        int kk = k0 + g*4;
        r.x = A[((kk+0)*V + i)*V + j] + lamv*(acc[g*4+0] + kb[kk+0]);
        r.y = A[((kk+1)*V + i)*V + j] + lamv*(acc[g*4+1] + kb[kk+1]);
        r.z = A[((kk+2)*V + i)*V + j] + lamv*(acc[g*4+2] + kb[kk+2]);
        r.w = A[((kk+3)*V + i)*V + j] + lamv*(acc[g*4+3] + kb[kk+3]);
        *(float4*)&g_Atil[outbase + g*4] = r;
    }
}

// ---------------- K4: gate[b][k] --------------------------------------------
__global__ void __launch_bounds__(512) k4_gate(
        const float* __restrict__ qw, const float* __restrict__ qb,
        const float* __restrict__ kw, const float* __restrict__ kb,
        const float* __restrict__ c1w, const float* __restrict__ c1b,
        const float* __restrict__ l1w, const float* __restrict__ l1b,
        const float* __restrict__ c2w, const float* __restrict__ c2b) {
    extern __shared__ float sm4[];
    float* Hb_s = sm4;
    float* Zb_s = Hb_s + 3200;
    float* XQ_s = Zb_s + 3200;
    float* XK_s = XQ_s + 3200;
    float* qw_s = XK_s + 3200;
    float* kw_s = qw_s + 4096;
    float* ca_s = kw_s + 4096;
    float* c1_s = ca_s + 512;

    int b = blockIdx.x, tid = threadIdx.x;
    int k = tid & 127, uh = tid >> 7;
    for (int lin = tid; lin < V*K; lin += 512) Hb_s[lin] = g_Hbar[b*V*K + lin];
    __syncthreads();

    int u_lo = (uh == 0) ? 0 : (7 + 6*(uh-1));
    int nu   = (uh == 0) ? 7 : 6;

    for (int ui = 0; ui < nu; ui++) {
        int u = u_lo + ui;
        float acc = 0.f;
        const float* ap = g_Atil + ((size_t)(b*V + u)*V)*K + k;
#pragma unroll
        for (int v = 0; v < V; v++) acc += ap[v*K] * Hb_s[v*K + k];
        Zb_s[u*K + k] = acc;
    }
    __syncthreads();

    float accq[7], acck[7];
    for (int ui = 0; ui < nu; ui++) { accq[ui] = qb[k]; acck[ui] = kb[k]; }
    for (int mc = 0; mc < K; mc += 32) {
        for (int lin = tid; lin < 32*128; lin += 512) {
            int mm = lin >> 7, kk = lin & 127;
            qw_s[lin] = qw[(mc + mm)*K + kk];
            kw_s[lin] = kw[(mc + mm)*K + kk];
        }
        __syncthreads();
        for (int ui = 0; ui < nu; ui++) {
            int u = u_lo + ui;
            float aq = accq[ui], ak = acck[ui];
#pragma unroll
            for (int mm = 0; mm < 32; mm++) {
                float z = Zb_s[u*K + mc + mm];
                aq += z * qw_s[mm*128 + k];
                ak += z * kw_s[mm*128 + k];
            }
            accq[ui] = aq; acck[ui] = ak;
        }
        __syncthreads();
    }
    for (int ui = 0; ui < nu; ui++) {
        XQ_s[(u_lo+ui)*K + k] = accq[ui];
        XK_s[(u_lo+ui)*K + k] = acck[ui];
    }
    __syncthreads();

    const float inv_scale = 1.0f / sqrtf((float)T);
    float ca = 0.f;
    for (int ui = 0; ui < nu; ui++) {
        int u = u_lo + ui;
        float xq = XQ_s[u*K + k];
        float mx = -1e30f;
#pragma unroll
        for (int v = 0; v < V; v++) {
            float s = xq * XK_s[v*K + k] * inv_scale;
            mx = fmaxf(mx, s);
        }
        float den = 0.f, num = 0.f;
#pragma unroll
        for (int v = 0; v < V; v++) {
            float s = xq * XK_s[v*K + k] * inv_scale;
            float e = expf(s - mx);
            den += e;
            num += e * Hb_s[v*K + k];
        }
        ca += num / den;
    }
    ca_s[tid] = ca;
    __syncthreads();
    if (tid < 128)
        ca_s[tid] = (ca_s[tid] + ca_s[tid+128] + ca_s[tid+256] + ca_s[tid+384]) * (1.0f/V);
    __syncthreads();

    if (tid < R) {
        float t = c1b[tid];
        for (int kk = 0; kk < K; kk++) t += ca_s[kk] * c1w[kk*R + tid];
        float mu = t;
#pragma unroll
        for (int o = 16; o > 0; o >>= 1) mu += __shfl_xor_sync(0xffffffffu, mu, o);
        mu *= (1.0f/R);
        float d = t - mu;
        float var = d*d;
#pragma unroll
        for (int o = 16; o > 0; o >>= 1) var += __shfl_xor_sync(0xffffffffu, var, o);
        var *= (1.0f/R);
        float y = d * rsqrtf(var + 1e-5f) * l1w[tid] + l1b[tid];
        c1_s[tid] = 0.5f * y * (1.0f + erff(y * 0.70710678118654752f));
    }
    __syncthreads();

    if (tid < 128) {
        float g = c2b[k];
#pragma unroll
        for (int r = 0; r < R; r++) g += c1_s[r] * c2w[r*K + k];
        g_gate[b*K + k] = 1.0f / (1.0f + expf(-g));
    }
}

// ---------------- K56: fused H-GEMM + gated GCN + LN (f32x2, 2 CTA/SM) ------
// TT=4 (100 rows/tile), 256 threads, 2048 blocks, ~98.6KB smem -> 2 CTA/SM.
// Phase A: warp w -> (t-group = w>>1, k-half = w&1); acc[25] ULL (50 regs).
//   x staged duplicated: one LDS.128 yields two (x,x) f32x2 operands.
// Phase B: kp = tid&63, tg = tid>>6 (0..3); z[25] ULL; dbl-buffered A stage.
#define TT 4
__global__ void __launch_bounds__(256, 2) k56_fused(
        const float* __restrict__ x,
        const float* __restrict__ xiw, const float* __restrict__ xib,
        const float* __restrict__ l2w, const float* __restrict__ l2b,
        float* __restrict__ out) {
    extern __shared__ float sm6[];
    float* Hs   = sm6;                 // 100*128 = 12800
    float* xs2  = Hs  + 12800;         // 100*32  = 3200 (dup)
    float* ws   = xs2 + 3200;          // 16*128  = 2048
    float* As0  = ws  + 2048;          // 3200
    float* As1  = As0 + 3200;          // 3200
    float* mu_s = As1 + 3200;          // 100
    float* rs_s = mu_s + 100;          // 100 (+pad)

    int b  = blockIdx.x >> 5;
    int tt = blockIdx.x & 31;
    int tid  = threadIdx.x;
    int wid  = tid >> 5, lane = tid & 31;

    // ---------- Phase A: H tile [100 x 128] = x_tile @ xi_w + bias (f32x2) --
    int ta = wid >> 1;                 // t-row group 0..3
    int kh = wid & 1;                  // k half
    int kc = kh*64 + lane*2;           // k pair (kc, kc+1)

    const size_t xbase = ((size_t)(b*T + tt*TT))*V*C;  // 100 contiguous rows

    unsigned long long acc[V];
#pragma unroll
    for (int v = 0; v < V; v++) acc[v] = 0ull;

    for (int cc = 0; cc < C; cc += 16) {
        // stage x chunk duplicated: xs2[r*32 + 2c] = xs2[...+1] = x(r, cc+c)
        for (int lin = tid; lin < 100*16; lin += 256) {
            int r = lin >> 4, c = lin & 15;
            float vx = x[xbase + (size_t)r*C + cc + c];
            *(float2*)&xs2[r*32 + 2*c] = make_float2(vx, vx);
        }
        // stage w chunk [16 c][128 k]
        for (int lin = tid; lin < 512; lin += 256) {
            int c = lin >> 5, k4 = (lin & 31) << 2;
            *(float4*)&ws[c*128 + k4] = *(const float4*)&xiw[(cc + c)*K + k4];
        }
        __syncthreads();
#pragma unroll
        for (int cg = 0; cg < 8; cg++) {
            int c0 = cg*2;
            unsigned long long w0 = *(const unsigned long long*)&ws[c0*128 + kc];
            unsigned long long w1 = *(const unsigned long long*)&ws[(c0+1)*128 + kc];
            const float* xr = &xs2[(ta*V)*32 + 2*c0];
#pragma unroll
            for (int v = 0; v < V; v++) {
                ulonglong2 xp = *(const ulonglong2*)&xr[v*32];
                acc[v] = fma2(xp.x, w0, acc[v]);
                acc[v] = fma2(xp.y, w1, acc[v]);
            }
        }
        __syncthreads();
    }

    // write H tile (+bias) to smem
    {
        float2 bias2 = *(const float2*)&xib[kc];
#pragma unroll
        for (int v = 0; v < V; v++) {
            float lo, hi;
            unpack2(acc[v], lo, hi);
            *(float2*)&Hs[(ta*V + v)*K + kc] = make_float2(lo + bias2.x, hi + bias2.y);
        }
    }
    __syncthreads();

    // ---------- Phase B: Z = gate * (A_tilde . H), LayerNorm over k ----------
    int kp = tid & 63;                 // k-pair index (k = 2*kp, 2*kp+1)
    int tg = tid >> 6;                 // local t (0..3)

    const float* Ab = g_Atil + (size_t)b*V*V*K;
    for (int lin = tid; lin < 800; lin += 256) {
        int u = lin >> 5, k4 = (lin & 31) << 2;
        *(float4*)&As0[u*K + k4] = *(const float4*)&Ab[((size_t)u*V + 0)*K + k4];
    }
    __syncthreads();

    unsigned long long z[V];
#pragma unroll
    for (int u = 0; u < V; u++) z[u] = 0ull;

    for (int v = 0; v < V; v++) {
        float* cur = (v & 1) ? As1 : As0;
        float* nxt = (v & 1) ? As0 : As1;
        if (v + 1 < V) {
            for (int lin = tid; lin < 800; lin += 256) {
                int u = lin >> 5, k4 = (lin & 31) << 2;
                *(float4*)&nxt[u*K + k4] = *(const float4*)&Ab[((size_t)u*V + (v+1))*K + k4];
            }
        }
        unsigned long long h = *(const unsigned long long*)&Hs[(tg*V + v)*K + 2*kp];
#pragma unroll
        for (int u = 0; u < V; u++) {
            unsigned long long a = *(const unsigned long long*)&cur[u*K + 2*kp];
            z[u] = fma2(h, a, z[u]);
        }
        __syncthreads();
    }

    float2 gk = *(const float2*)&g_gate[b*K + 2*kp];
#pragma unroll
    for (int u = 0; u < V; u++) {
        float zl, zh;
        unpack2(z[u], zl, zh);
        *(float2*)&Hs[(tg*V + u)*K + 2*kp] = make_float2(zl * gk.x, zh * gk.y);
    }
    __syncthreads();

    // LayerNorm stats (rotated k-scan: conflict-free)
    for (int p = tid; p < TT*V; p += 256) {
        float s = 0.f, s2 = 0.f;
        for (int kk = 0; kk < K; kk++) {
            int k = (kk + p) & 127;
            float val = Hs[p*K + k];
            s += val; s2 += val*val;
        }
        float m = s * (1.0f/K);
        float var = s2 * (1.0f/K) - m*m;
        mu_s[p] = m;
        rs_s[p] = rsqrtf(var + 1e-5f);
    }
    __syncthreads();

    const size_t obase = ((size_t)(b*T + tt*TT))*V*K;
    for (int lin = tid; lin < TT*V*K; lin += 256) {
        int r = lin >> 7, kk = lin & 127;
        float val = (Hs[lin] - mu_s[r]) * rs_s[r];
        out[obase + lin] = val * l2w[kk] + l2b[kk];
    }
}

// ---------------- launch ----------------------------------------------------
extern "C" void kernel_launch(void* const* d_in, const int* in_sizes, int n_in,
                              void* d_out, int out_size) {
    const float* x    = (const float*)d_in[0];
    const float* A    = (const float*)d_in[1];
    const float* lam  = (const float*)d_in[2];
    const float* phiw = (const float*)d_in[3];
    const float* phib = (const float*)d_in[4];
    const float* thw  = (const float*)d_in[5];
    const float* thb  = (const float*)d_in[6];
    const float* kapw = (const float*)d_in[7];
    const float* kapb = (const float*)d_in[8];
    const float* xiw  = (const float*)d_in[9];
    const float* xib  = (const float*)d_in[10];
    const float* qw   = (const float*)d_in[11];
    const float* qb   = (const float*)d_in[12];
    const float* kw   = (const float*)d_in[13];
    const float* kb   = (const float*)d_in[14];
    const float* c1w  = (const float*)d_in[15];
    const float* c1b  = (const float*)d_in[16];
    const float* l1w  = (const float*)d_in[17];
    const float* l1b  = (const float*)d_in[18];
    const float* c2w  = (const float*)d_in[19];
    const float* c2b  = (const float*)d_in[20];
    const float* l2w  = (const float*)d_in[21];
    const float* l2b  = (const float*)d_in[22];
    float* out = (float*)d_out;

    size_t sm2  = (size_t)(3200 + 16384) * 4;
    size_t sm3  = (size_t)(16384 + 32*FPAD) * 4;
    size_t sm4  = (size_t)(4*3200 + 2*4096 + 512 + 32) * 4;
    size_t sm56 = (size_t)(12800 + 3200 + 2048 + 3200 + 3200 + 100 + 108) * 4;

    cudaFuncSetAttribute(k2_small,  cudaFuncAttributeMaxDynamicSharedMemorySize, (int)sm2);
    cudaFuncSetAttribute(k3_atilde, cudaFuncAttributeMaxDynamicSharedMemorySize, (int)sm3);
    cudaFuncSetAttribute(k4_gate,   cudaFuncAttributeMaxDynamicSharedMemorySize, (int)sm4);
    cudaFuncSetAttribute(k56_fused, cudaFuncAttributeMaxDynamicSharedMemorySize, (int)sm56);

    k1_xbar<<<B*V, 128>>>(x);
    k2_small<<<B, 256, sm2>>>(phiw, phib, thw, thb, xiw, xib);
    k3_atilde<<<B*20, 256, sm3>>>(A, lam, kapw, kapb);
    k4_gate<<<B, 512, sm4>>>(qw, qb, kw, kb, c1w, c1b, l1w, l1b, c2w, c2b);
    k56_fused<<<B*32, 256, sm56>>>(x, xiw, xib, l2w, l2b, out);
}

// round 13
// speedup vs baseline: 1.7663x; 1.2249x over previous
#include <cuda_runtime.h>
#include <math.h>

#define B 64
#define T 128
#define V 25
#define C 128
#define K 128
#define R 32

// ---------------- scratch (device globals; no allocations allowed) ----------
__device__ float g_phi [B*V*K];
__device__ float g_theta[B*V*K];
__device__ float g_Hbar[B*V*K];
__device__ float g_Atil[B*V*V*K];      // [b][u][v][k]
__device__ float g_gate[B*K];

// f32x2 packed FMA (SASS FFMA2) -- exact fp32, 2x FFMA-pipe rate
__device__ __forceinline__ unsigned long long fma2(unsigned long long a,
                                                   unsigned long long b,
                                                   unsigned long long c) {
    unsigned long long d;
    asm("fma.rn.f32x2 %0, %1, %2, %3;" : "=l"(d) : "l"(a), "l"(b), "l"(c));
    return d;
}
__device__ __forceinline__ void unpack2(unsigned long long p, float& lo, float& hi) {
    asm("mov.b64 {%0,%1}, %2;" : "=f"(lo), "=f"(hi) : "l"(p));
}
__device__ __forceinline__ unsigned int smem_u32(const void* p) {
    unsigned int a;
    asm("{ .reg .u64 t; cvta.to.shared.u64 t, %1; cvt.u32.u64 %0, t; }"
        : "=r"(a) : "l"(p));
    return a;
}
// cp.async of 16 BYTES (4 floats)
#define CP_ASYNC16(sa, gp) \
    asm volatile("cp.async.ca.shared.global [%0], [%1], 16;" \
                 :: "r"(sa), "l"(gp) : "memory")
#define CP_COMMIT() asm volatile("cp.async.commit_group;" ::: "memory")
#define CP_WAIT0()  asm volatile("cp.async.wait_group 0;" ::: "memory")

// ---------------- K2: xbar (in-block) -> phi_x / theta_x / Hbar -------------
__global__ void k2_small(const float* __restrict__ x,
                         const float* __restrict__ pw, const float* __restrict__ pb,
                         const float* __restrict__ tw, const float* __restrict__ tb,
                         const float* __restrict__ xw, const float* __restrict__ xb2) {
    extern __shared__ float sm2[];
    float* xb_s = sm2;            // 3200
    float* W_s  = sm2 + 3200;     // 16384
    int b = blockIdx.x, tid = threadIdx.x;

    // xbar = mean_t x[b]
    for (int lin = tid; lin < V*C; lin += 256) {
        const float* p = x + ((size_t)(b*T))*V*C + lin;
        float s0 = 0.f, s1 = 0.f, s2 = 0.f, s3 = 0.f;
#pragma unroll 4
        for (int t = 0; t < T; t += 4) {
            s0 += p[(size_t)(t+0)*V*C];
            s1 += p[(size_t)(t+1)*V*C];
            s2 += p[(size_t)(t+2)*V*C];
            s3 += p[(size_t)(t+3)*V*C];
        }
        xb_s[lin] = (s0 + s1 + s2 + s3) * (1.0f/T);
    }

    const float* Wp[3] = {pw, tw, xw};
    const float* Bp[3] = {pb, tb, xb2};
    float* Op[3];
    Op[0] = g_phi; Op[1] = g_theta; Op[2] = g_Hbar;

    for (int w = 0; w < 3; w++) {
        for (int lin = tid; lin < C*K; lin += 256) W_s[lin] = Wp[w][lin];
        __syncthreads();
        for (int task = tid; task < V*(K/4); task += 256) {
            int v  = task >> 5;
            int k4 = (task & 31) << 2;
            float4 acc = *(const float4*)&Bp[w][k4];
            for (int c = 0; c < C; c++) {
                float a = xb_s[v*C + c];
                float4 wv = *(const float4*)&W_s[c*K + k4];
                acc.x += a*wv.x; acc.y += a*wv.y; acc.z += a*wv.z; acc.w += a*wv.w;
            }
            *(float4*)&Op[w][b*V*K + v*K + k4] = acc;
        }
        __syncthreads();
    }
}

// ---------------- K3: A_tilde ----------------------------------------------
#define PAIRS_PER_BLK 32
#define FPAD 132
__global__ void k3_atilde(const float* __restrict__ A, const float* __restrict__ lam_p,
                          const float* __restrict__ kw, const float* __restrict__ kb) {
    extern __shared__ float sm3[];
    float* kap_s = sm3;
    float* F_s   = sm3 + C*K;
    int b = blockIdx.x / 20;
    int chunk = blockIdx.x % 20;
    int tid = threadIdx.x;

    for (int lin = tid; lin < K*K; lin += 256) kap_s[lin] = kw[lin];

    for (int idx = tid; idx < PAIRS_PER_BLK*K; idx += 256) {
        int p = idx >> 7, m = idx & 127;
        int pair = chunk*PAIRS_PER_BLK + p;
        float f = 0.f;
        if (pair < V*V) {
            int i = pair / V, j = pair % V;
            f = tanhf(g_phi[(b*V+i)*K + m] - g_theta[(b*V+j)*K + m]);
        }
        F_s[p*FPAD + m] = f;
    }
    __syncthreads();

    int wid = tid >> 5, lane = tid & 31;
    int k0 = wid * 16;
    int pair = chunk*PAIRS_PER_BLK + lane;
    if (pair >= V*V) return;

    float acc[16];
#pragma unroll
    for (int q = 0; q < 16; q++) acc[q] = 0.f;

    for (int m = 0; m < K; m += 4) {
        float4 f4 = *(const float4*)&F_s[lane*FPAD + m];
#pragma unroll
        for (int g = 0; g < 4; g++) {
            float4 r0 = *(const float4*)&kap_s[(m+0)*K + k0 + g*4];
            float4 r1 = *(const float4*)&kap_s[(m+1)*K + k0 + g*4];
            float4 r2 = *(const float4*)&kap_s[(m+2)*K + k0 + g*4];
            float4 r3 = *(const float4*)&kap_s[(m+3)*K + k0 + g*4];
            acc[g*4+0] += f4.x*r0.x + f4.y*r1.x + f4.z*r2.x + f4.w*r3.x;
            acc[g*4+1] += f4.x*r0.y + f4.y*r1.y + f4.z*r2.y + f4.w*r3.y;
            acc[g*4+2] += f4.x*r0.z + f4.y*r1.z + f4.z*r2.z + f4.w*r3.z;
            acc[g*4+3] += f4.x*r0.w + f4.y*r1.w + f4.z*r2.w + f4.w*r3.w;
        }
    }

    float lamv = *lam_p;
    int i = pair / V, j = pair % V;
    int outbase = ((b*V + i)*V + j)*K + k0;
#pragma unroll
    for (int g = 0; g < 4; g++) {
        float4 r;
        int kk = k0 + g*4;
        r.x = A[((kk+0)*V + i)*V + j] + lamv*(acc[g*4+0] + kb[kk+0]);
        r.y = A[((kk+1)*V + i)*V + j] + lamv*(acc[g*4+1] + kb[kk+1]);
        r.z = A[((kk+2)*V + i)*V + j] + lamv*(acc[g*4+2] + kb[kk+2]);
        r.w = A[((kk+3)*V + i)*V + j] + lamv*(acc[g*4+3] + kb[kk+3]);
        *(float4*)&g_Atil[outbase + g*4] = r;
    }
}

// ---------------- K4: gate[b][k] --------------------------------------------
__global__ void __launch_bounds__(512) k4_gate(
        const float* __restrict__ qw, const float* __restrict__ qb,
        const float* __restrict__ kw, const float* __restrict__ kb,
        const float* __restrict__ c1w, const float* __restrict__ c1b,
        const float* __restrict__ l1w, const float* __restrict__ l1b,
        const float* __restrict__ c2w, const float* __restrict__ c2b) {
    extern __shared__ float sm4[];
    float* Hb_s = sm4;
    float* Zb_s = Hb_s + 3200;
    float* XQ_s = Zb_s + 3200;
    float* XK_s = XQ_s + 3200;
    float* qw_s = XK_s + 3200;
    float* kw_s = qw_s + 4096;
    float* ca_s = kw_s + 4096;
    float* c1_s = ca_s + 512;

    int b = blockIdx.x, tid = threadIdx.x;
    int k = tid & 127, uh = tid >> 7;
    for (int lin = tid; lin < V*K; lin += 512) Hb_s[lin] = g_Hbar[b*V*K + lin];
    __syncthreads();

    int u_lo = (uh == 0) ? 0 : (7 + 6*(uh-1));
    int nu   = (uh == 0) ? 7 : 6;

    for (int ui = 0; ui < nu; ui++) {
        int u = u_lo + ui;
        float acc = 0.f;
        const float* ap = g_Atil + ((size_t)(b*V + u)*V)*K + k;
#pragma unroll
        for (int v = 0; v < V; v++) acc += ap[v*K] * Hb_s[v*K + k];
        Zb_s[u*K + k] = acc;
    }
    __syncthreads();

    float accq[7], acck[7];
    for (int ui = 0; ui < nu; ui++) { accq[ui] = qb[k]; acck[ui] = kb[k]; }
    for (int mc = 0; mc < K; mc += 32) {
        for (int lin = tid; lin < 32*128; lin += 512) {
            int mm = lin >> 7, kk = lin & 127;
            qw_s[lin] = qw[(mc + mm)*K + kk];
            kw_s[lin] = kw[(mc + mm)*K + kk];
        }
        __syncthreads();
        for (int ui = 0; ui < nu; ui++) {
            int u = u_lo + ui;
            float aq = accq[ui], ak = acck[ui];
#pragma unroll
            for (int mm = 0; mm < 32; mm++) {
                float z = Zb_s[u*K + mc + mm];
                aq += z * qw_s[mm*128 + k];
                ak += z * kw_s[mm*128 + k];
            }
            accq[ui] = aq; acck[ui] = ak;
        }
        __syncthreads();
    }
    for (int ui = 0; ui < nu; ui++) {
        XQ_s[(u_lo+ui)*K + k] = accq[ui];
        XK_s[(u_lo+ui)*K + k] = acck[ui];
    }
    __syncthreads();

    const float inv_scale = 1.0f / sqrtf((float)T);
    float ca = 0.f;
    for (int ui = 0; ui < nu; ui++) {
        int u = u_lo + ui;
        float xq = XQ_s[u*K + k];
        float mx = -1e30f;
#pragma unroll
        for (int v = 0; v < V; v++) {
            float s = xq * XK_s[v*K + k] * inv_scale;
            mx = fmaxf(mx, s);
        }
        float den = 0.f, num = 0.f;
#pragma unroll
        for (int v = 0; v < V; v++) {
            float s = xq * XK_s[v*K + k] * inv_scale;
            float e = expf(s - mx);
            den += e;
            num += e * Hb_s[v*K + k];
        }
        ca += num / den;
    }
    ca_s[tid] = ca;
    __syncthreads();
    if (tid < 128)
        ca_s[tid] = (ca_s[tid] + ca_s[tid+128] + ca_s[tid+256] + ca_s[tid+384]) * (1.0f/V);
    __syncthreads();

    if (tid < R) {
        float t = c1b[tid];
        for (int kk = 0; kk < K; kk++) t += ca_s[kk] * c1w[kk*R + tid];
        float mu = t;
#pragma unroll
        for (int o = 16; o > 0; o >>= 1) mu += __shfl_xor_sync(0xffffffffu, mu, o);
        mu *= (1.0f/R);
        float d = t - mu;
        float var = d*d;
#pragma unroll
        for (int o = 16; o > 0; o >>= 1) var += __shfl_xor_sync(0xffffffffu, var, o);
        var *= (1.0f/R);
        float y = d * rsqrtf(var + 1e-5f) * l1w[tid] + l1b[tid];
        c1_s[tid] = 0.5f * y * (1.0f + erff(y * 0.70710678118654752f));
    }
    __syncthreads();

    if (tid < 128) {
        float g = c2b[k];
#pragma unroll
        for (int r = 0; r < R; r++) g += c1_s[r] * c2w[r*K + k];
        g_gate[b*K + k] = 1.0f / (1.0f + expf(-g));
    }
}

// ---------------- K56: fused H-GEMM + gated GCN + LN (f32x2, 2 CTA/SM) ------
#define TT 4
__global__ void __launch_bounds__(256, 2) k56_fused(
        const float* __restrict__ x,
        const float* __restrict__ xiw, const float* __restrict__ xib,
        const float* __restrict__ l2w, const float* __restrict__ l2b,
        float* __restrict__ out) {
    extern __shared__ float sm6[];
    float* Hs   = sm6;                 // 100*128 = 12800
    float* xs2  = Hs  + 12800;         // 100*32  = 3200 (dup)
    float* ws   = xs2 + 3200;          // 16*128  = 2048
    float* As0  = ws  + 2048;          // 3200
    float* As1  = As0 + 3200;          // 3200
    float* mu_s = As1 + 3200;          // 100
    float* rs_s = mu_s + 100;          // 100 (+pad)

    int b  = blockIdx.x >> 5;
    int tt = blockIdx.x & 31;
    int tid  = threadIdx.x;
    int wid  = tid >> 5, lane = tid & 31;

    // ---------- Phase A: H tile [100 x 128] = x_tile @ xi_w + bias (f32x2) --
    int ta = wid >> 1;                 // t-row group 0..3
    int kh = wid & 1;                  // k half
    int kc = kh*64 + lane*2;           // k pair (kc, kc+1)

    const size_t xbase = ((size_t)(b*T + tt*TT))*V*C;  // 100 contiguous rows
    unsigned int ws_sa = smem_u32(ws);

    unsigned long long acc[V];
#pragma unroll
    for (int v = 0; v < V; v++) acc[v] = 0ull;

    for (int cc = 0; cc < C; cc += 16) {
        // w chunk via cp.async: 2048 floats = 512 x 16B chunks
        for (int lin = tid; lin < 512; lin += 256) {
            int c = lin >> 5, f4 = (lin & 31) << 2;
            CP_ASYNC16(ws_sa + (c*128 + f4)*4, &xiw[(cc + c)*K + f4]);
        }
        CP_COMMIT();
        // x chunk duplicated (float4 LDG -> 4 dup float2 stores)
        for (int lin = tid; lin < 400; lin += 256) {
            int r = lin >> 2, c4 = (lin & 3) << 2;
            float4 xv = *(const float4*)&x[xbase + (size_t)r*C + cc + c4];
            float* d = &xs2[r*32 + 2*c4];
            *(float2*)&d[0] = make_float2(xv.x, xv.x);
            *(float2*)&d[2] = make_float2(xv.y, xv.y);
            *(float2*)&d[4] = make_float2(xv.z, xv.z);
            *(float2*)&d[6] = make_float2(xv.w, xv.w);
        }
        CP_WAIT0();
        __syncthreads();
#pragma unroll
        for (int cg = 0; cg < 8; cg++) {
            int c0 = cg*2;
            unsigned long long w0 = *(const unsigned long long*)&ws[c0*128 + kc];
            unsigned long long w1 = *(const unsigned long long*)&ws[(c0+1)*128 + kc];
            const float* xr = &xs2[(ta*V)*32 + 2*c0];
#pragma unroll
            for (int v = 0; v < V; v++) {
                ulonglong2 xp = *(const ulonglong2*)&xr[v*32];
                acc[v] = fma2(xp.x, w0, acc[v]);
                acc[v] = fma2(xp.y, w1, acc[v]);
            }
        }
        __syncthreads();
    }

    // write H tile (+bias) to smem
    {
        float2 bias2 = *(const float2*)&xib[kc];
#pragma unroll
        for (int v = 0; v < V; v++) {
            float lo, hi;
            unpack2(acc[v], lo, hi);
            *(float2*)&Hs[(ta*V + v)*K + kc] = make_float2(lo + bias2.x, hi + bias2.y);
        }
    }

    // ---------- Phase B: Z = gate * (A_tilde . H), LayerNorm over k ----------
    int kp = tid & 63;                 // k-pair index (k = 2*kp, 2*kp+1)
    int tg = tid >> 6;                 // local t (0..3)

    const float* Ab = g_Atil + (size_t)b*V*V*K;
    unsigned int a_sa[2];
    a_sa[0] = smem_u32(As0);
    a_sa[1] = smem_u32(As1);

    // prologue: stage v=0 into As0: 3200 floats = 800 x 16B chunks
    for (int lin = tid; lin < 800; lin += 256) {
        int u = lin >> 5, f4 = (lin & 31) << 2;
        CP_ASYNC16(a_sa[0] + (u*K + f4)*4, &Ab[((size_t)u*V + 0)*K + f4]);
    }
    CP_COMMIT();
    CP_WAIT0();
    __syncthreads();

    unsigned long long z[V];
#pragma unroll
    for (int u = 0; u < V; u++) z[u] = 0ull;

    for (int v = 0; v < V; v++) {
        const float* cur = (v & 1) ? As1 : As0;
        unsigned int nxt_sa = a_sa[(v & 1) ^ 1];
        if (v + 1 < V) {
            for (int lin = tid; lin < 800; lin += 256) {
                int u = lin >> 5, f4 = (lin & 31) << 2;
                CP_ASYNC16(nxt_sa + (u*K + f4)*4, &Ab[((size_t)u*V + (v+1))*K + f4]);
            }
            CP_COMMIT();
        }
        unsigned long long h = *(const unsigned long long*)&Hs[(tg*V + v)*K + 2*kp];
#pragma unroll
        for (int u = 0; u < V; u++) {
            unsigned long long a = *(const unsigned long long*)&cur[u*K + 2*kp];
            z[u] = fma2(h, a, z[u]);
        }
        CP_WAIT0();
        __syncthreads();
    }

    float2 gk = *(const float2*)&g_gate[b*K + 2*kp];
#pragma unroll
    for (int u = 0; u < V; u++) {
        float zl, zh;
        unpack2(z[u], zl, zh);
        *(float2*)&Hs[(tg*V + u)*K + 2*kp] = make_float2(zl * gk.x, zh * gk.y);
    }
    __syncthreads();

    // LayerNorm stats (rotated k-scan: conflict-free)
    for (int p = tid; p < TT*V; p += 256) {
        float s = 0.f, s2 = 0.f;
        for (int kk = 0; kk < K; kk++) {
            int k = (kk + p) & 127;
            float val = Hs[p*K + k];
            s += val; s2 += val*val;
        }
        float m = s * (1.0f/K);
        float var = s2 * (1.0f/K) - m*m;
        mu_s[p] = m;
        rs_s[p] = rsqrtf(var + 1e-5f);
    }
    __syncthreads();

    const size_t obase = ((size_t)(b*T + tt*TT))*V*K;
    for (int lin = tid; lin < TT*V*K; lin += 256) {
        int r = lin >> 7, kk = lin & 127;
        float val = (Hs[lin] - mu_s[r]) * rs_s[r];
        out[obase + lin] = val * l2w[kk] + l2b[kk];
    }
}

// ---------------- launch ----------------------------------------------------
extern "C" void kernel_launch(void* const* d_in, const int* in_sizes, int n_in,
                              void* d_out, int out_size) {
    const float* x    = (const float*)d_in[0];
    const float* A    = (const float*)d_in[1];
    const float* lam  = (const float*)d_in[2];
    const float* phiw = (const float*)d_in[3];
    const float* phib = (const float*)d_in[4];
    const float* thw  = (const float*)d_in[5];
    const float* thb  = (const float*)d_in[6];
    const float* kapw = (const float*)d_in[7];
    const float* kapb = (const float*)d_in[8];
    const float* xiw  = (const float*)d_in[9];
    const float* xib  = (const float*)d_in[10];
    const float* qw   = (const float*)d_in[11];
    const float* qb   = (const float*)d_in[12];
    const float* kw   = (const float*)d_in[13];
    const float* kb   = (const float*)d_in[14];
    const float* c1w  = (const float*)d_in[15];
    const float* c1b  = (const float*)d_in[16];
    const float* l1w  = (const float*)d_in[17];
    const float* l1b  = (const float*)d_in[18];
    const float* c2w  = (const float*)d_in[19];
    const float* c2b  = (const float*)d_in[20];
    const float* l2w  = (const float*)d_in[21];
    const float* l2b  = (const float*)d_in[22];
    float* out = (float*)d_out;

    size_t sm2  = (size_t)(3200 + 16384) * 4;
    size_t sm3  = (size_t)(16384 + 32*FPAD) * 4;
    size_t sm4  = (size_t)(4*3200 + 2*4096 + 512 + 32) * 4;
    size_t sm56 = (size_t)(12800 + 3200 + 2048 + 3200 + 3200 + 100 + 108) * 4;

    cudaFuncSetAttribute(k2_small,  cudaFuncAttributeMaxDynamicSharedMemorySize, (int)sm2);
    cudaFuncSetAttribute(k3_atilde, cudaFuncAttributeMaxDynamicSharedMemorySize, (int)sm3);
    cudaFuncSetAttribute(k4_gate,   cudaFuncAttributeMaxDynamicSharedMemorySize, (int)sm4);
    cudaFuncSetAttribute(k56_fused, cudaFuncAttributeMaxDynamicSharedMemorySize, (int)sm56);

    k2_small<<<B, 256, sm2>>>(x, phiw, phib, thw, thb, xiw, xib);
    k3_atilde<<<B*20, 256, sm3>>>(A, lam, kapw, kapb);
    k4_gate<<<B, 512, sm4>>>(qw, qb, kw, kb, c1w, c1b, l1w, l1b, c2w, c2b);
    k56_fused<<<B*32, 256, sm56>>>(x, xiw, xib, l2w, l2b, out);
}

// round 14
// speedup vs baseline: 2.0023x; 1.1336x over previous
#include <cuda_runtime.h>
#include <math.h>

#define B 64
#define T 128
#define V 25
#define C 128
#define K 128
#define R 32

// ---------------- scratch (device globals; no allocations allowed) ----------
__device__ float g_phi [B*V*K];
__device__ float g_theta[B*V*K];
__device__ float g_Hbar[B*V*K];
__device__ float g_Atil[B*V*V*K];      // [b][u][v][k]
__device__ float g_gate[B*K];

// f32x2 packed FMA (SASS FFMA2) -- exact fp32, 2x FFMA-pipe rate
__device__ __forceinline__ unsigned long long fma2(unsigned long long a,
                                                   unsigned long long b,
                                                   unsigned long long c) {
    unsigned long long d;
    asm("fma.rn.f32x2 %0, %1, %2, %3;" : "=l"(d) : "l"(a), "l"(b), "l"(c));
    return d;
}
__device__ __forceinline__ void unpack2(unsigned long long p, float& lo, float& hi) {
    asm("mov.b64 {%0,%1}, %2;" : "=f"(lo), "=f"(hi) : "l"(p));
}
__device__ __forceinline__ unsigned int smem_u32(const void* p) {
    unsigned int a;
    asm("{ .reg .u64 t; cvta.to.shared.u64 t, %1; cvt.u32.u64 %0, t; }"
        : "=r"(a) : "l"(p));
    return a;
}
// cp.async of 16 BYTES (4 floats)
#define CP_ASYNC16(sa, gp) \
    asm volatile("cp.async.ca.shared.global [%0], [%1], 16;" \
                 :: "r"(sa), "l"(gp) : "memory")
#define CP_COMMIT() asm volatile("cp.async.commit_group;" ::: "memory")
#define CP_WAIT0()  asm volatile("cp.async.wait_group 0;" ::: "memory")

// ---------------- K2: xbar (in-block) -> phi_x / theta_x / Hbar -------------
__global__ void k2_small(const float* __restrict__ x,
                         const float* __restrict__ pw, const float* __restrict__ pb,
                         const float* __restrict__ tw, const float* __restrict__ tb,
                         const float* __restrict__ xw, const float* __restrict__ xb2) {
    extern __shared__ float sm2[];
    float* xb_s = sm2;            // 3200
    float* W_s  = sm2 + 3200;     // 16384
    int b = blockIdx.x, tid = threadIdx.x;

    for (int lin = tid; lin < V*C; lin += 256) {
        const float* p = x + ((size_t)(b*T))*V*C + lin;
        float s0 = 0.f, s1 = 0.f, s2 = 0.f, s3 = 0.f;
#pragma unroll 4
        for (int t = 0; t < T; t += 4) {
            s0 += p[(size_t)(t+0)*V*C];
            s1 += p[(size_t)(t+1)*V*C];
            s2 += p[(size_t)(t+2)*V*C];
            s3 += p[(size_t)(t+3)*V*C];
        }
        xb_s[lin] = (s0 + s1 + s2 + s3) * (1.0f/T);
    }

    const float* Wp[3] = {pw, tw, xw};
    const float* Bp[3] = {pb, tb, xb2};
    float* Op[3];
    Op[0] = g_phi; Op[1] = g_theta; Op[2] = g_Hbar;

    for (int w = 0; w < 3; w++) {
        for (int lin = tid; lin < C*K; lin += 256) W_s[lin] = Wp[w][lin];
        __syncthreads();
        for (int task = tid; task < V*(K/4); task += 256) {
            int v  = task >> 5;
            int k4 = (task & 31) << 2;
            float4 acc = *(const float4*)&Bp[w][k4];
            for (int c = 0; c < C; c++) {
                float a = xb_s[v*C + c];
                float4 wv = *(const float4*)&W_s[c*K + k4];
                acc.x += a*wv.x; acc.y += a*wv.y; acc.z += a*wv.z; acc.w += a*wv.w;
            }
            *(float4*)&Op[w][b*V*K + v*K + k4] = acc;
        }
        __syncthreads();
    }
}

// ---------------- K3: A_tilde ----------------------------------------------
#define PAIRS_PER_BLK 32
#define FPAD 132
__global__ void k3_atilde(const float* __restrict__ A, const float* __restrict__ lam_p,
                          const float* __restrict__ kw, const float* __restrict__ kb) {
    extern __shared__ float sm3[];
    float* kap_s = sm3;
    float* F_s   = sm3 + C*K;
    int b = blockIdx.x / 20;
    int chunk = blockIdx.x % 20;
    int tid = threadIdx.x;

    for (int lin = tid; lin < K*K; lin += 256) kap_s[lin] = kw[lin];

    for (int idx = tid; idx < PAIRS_PER_BLK*K; idx += 256) {
        int p = idx >> 7, m = idx & 127;
        int pair = chunk*PAIRS_PER_BLK + p;
        float f = 0.f;
        if (pair < V*V) {
            int i = pair / V, j = pair % V;
            f = tanhf(g_phi[(b*V+i)*K + m] - g_theta[(b*V+j)*K + m]);
        }
        F_s[p*FPAD + m] = f;
    }
    __syncthreads();

    int wid = tid >> 5, lane = tid & 31;
    int k0 = wid * 16;
    int pair = chunk*PAIRS_PER_BLK + lane;
    if (pair >= V*V) return;

    float acc[16];
#pragma unroll
    for (int q = 0; q < 16; q++) acc[q] = 0.f;

    for (int m = 0; m < K; m += 4) {
        float4 f4 = *(const float4*)&F_s[lane*FPAD + m];
#pragma unroll
        for (int g = 0; g < 4; g++) {
            float4 r0 = *(const float4*)&kap_s[(m+0)*K + k0 + g*4];
            float4 r1 = *(const float4*)&kap_s[(m+1)*K + k0 + g*4];
            float4 r2 = *(const float4*)&kap_s[(m+2)*K + k0 + g*4];
            float4 r3 = *(const float4*)&kap_s[(m+3)*K + k0 + g*4];
            acc[g*4+0] += f4.x*r0.x + f4.y*r1.x + f4.z*r2.x + f4.w*r3.x;
            acc[g*4+1] += f4.x*r0.y + f4.y*r1.y + f4.z*r2.y + f4.w*r3.y;
            acc[g*4+2] += f4.x*r0.z + f4.y*r1.z + f4.z*r2.z + f4.w*r3.z;
            acc[g*4+3] += f4.x*r0.w + f4.y*r1.w + f4.z*r2.w + f4.w*r3.w;
        }
    }

    float lamv = *lam_p;
    int i = pair / V, j = pair % V;
    int outbase = ((b*V + i)*V + j)*K + k0;
#pragma unroll
    for (int g = 0; g < 4; g++) {
        float4 r;
        int kk = k0 + g*4;
        r.x = A[((kk+0)*V + i)*V + j] + lamv*(acc[g*4+0] + kb[kk+0]);
        r.y = A[((kk+1)*V + i)*V + j] + lamv*(acc[g*4+1] + kb[kk+1]);
        r.z = A[((kk+2)*V + i)*V + j] + lamv*(acc[g*4+2] + kb[kk+2]);
        r.w = A[((kk+3)*V + i)*V + j] + lamv*(acc[g*4+3] + kb[kk+3]);
        *(float4*)&g_Atil[outbase + g*4] = r;
    }
}

// ---------------- K4: gate[b][k] --------------------------------------------
__global__ void __launch_bounds__(512) k4_gate(
        const float* __restrict__ qw, const float* __restrict__ qb,
        const float* __restrict__ kw, const float* __restrict__ kb,
        const float* __restrict__ c1w, const float* __restrict__ c1b,
        const float* __restrict__ l1w, const float* __restrict__ l1b,
        const float* __restrict__ c2w, const float* __restrict__ c2b) {
    extern __shared__ float sm4[];
    float* Hb_s = sm4;
    float* Zb_s = Hb_s + 3200;
    float* XQ_s = Zb_s + 3200;
    float* XK_s = XQ_s + 3200;
    float* qw_s = XK_s + 3200;
    float* kw_s = qw_s + 4096;
    float* ca_s = kw_s + 4096;
    float* c1_s = ca_s + 512;

    int b = blockIdx.x, tid = threadIdx.x;
    int k = tid & 127, uh = tid >> 7;
    for (int lin = tid; lin < V*K; lin += 512) Hb_s[lin] = g_Hbar[b*V*K + lin];
    __syncthreads();

    int u_lo = (uh == 0) ? 0 : (7 + 6*(uh-1));
    int nu   = (uh == 0) ? 7 : 6;

    for (int ui = 0; ui < nu; ui++) {
        int u = u_lo + ui;
        float acc = 0.f;
        const float* ap = g_Atil + ((size_t)(b*V + u)*V)*K + k;
#pragma unroll
        for (int v = 0; v < V; v++) acc += ap[v*K] * Hb_s[v*K + k];
        Zb_s[u*K + k] = acc;
    }
    __syncthreads();

    float accq[7], acck[7];
    for (int ui = 0; ui < nu; ui++) { accq[ui] = qb[k]; acck[ui] = kb[k]; }
    for (int mc = 0; mc < K; mc += 32) {
        for (int lin = tid; lin < 32*128; lin += 512) {
            int mm = lin >> 7, kk = lin & 127;
            qw_s[lin] = qw[(mc + mm)*K + kk];
            kw_s[lin] = kw[(mc + mm)*K + kk];
        }
        __syncthreads();
        for (int ui = 0; ui < nu; ui++) {
            int u = u_lo + ui;
            float aq = accq[ui], ak = acck[ui];
#pragma unroll
            for (int mm = 0; mm < 32; mm++) {
                float z = Zb_s[u*K + mc + mm];
                aq += z * qw_s[mm*128 + k];
                ak += z * kw_s[mm*128 + k];
            }
            accq[ui] = aq; acck[ui] = ak;
        }
        __syncthreads();
    }
    for (int ui = 0; ui < nu; ui++) {
        XQ_s[(u_lo+ui)*K + k] = accq[ui];
        XK_s[(u_lo+ui)*K + k] = acck[ui];
    }
    __syncthreads();

    const float inv_scale = 1.0f / sqrtf((float)T);
    float ca = 0.f;
    for (int ui = 0; ui < nu; ui++) {
        int u = u_lo + ui;
        float xq = XQ_s[u*K + k];
        float mx = -1e30f;
#pragma unroll
        for (int v = 0; v < V; v++) {
            float s = xq * XK_s[v*K + k] * inv_scale;
            mx = fmaxf(mx, s);
        }
        float den = 0.f, num = 0.f;
#pragma unroll
        for (int v = 0; v < V; v++) {
            float s = xq * XK_s[v*K + k] * inv_scale;
            float e = expf(s - mx);
            den += e;
            num += e * Hb_s[v*K + k];
        }
        ca += num / den;
    }
    ca_s[tid] = ca;
    __syncthreads();
    if (tid < 128)
        ca_s[tid] = (ca_s[tid] + ca_s[tid+128] + ca_s[tid+256] + ca_s[tid+384]) * (1.0f/V);
    __syncthreads();

    if (tid < R) {
        float t = c1b[tid];
        for (int kk = 0; kk < K; kk++) t += ca_s[kk] * c1w[kk*R + tid];
        float mu = t;
#pragma unroll
        for (int o = 16; o > 0; o >>= 1) mu += __shfl_xor_sync(0xffffffffu, mu, o);
        mu *= (1.0f/R);
        float d = t - mu;
        float var = d*d;
#pragma unroll
        for (int o = 16; o > 0; o >>= 1) var += __shfl_xor_sync(0xffffffffu, var, o);
        var *= (1.0f/R);
        float y = d * rsqrtf(var + 1e-5f) * l1w[tid] + l1b[tid];
        c1_s[tid] = 0.5f * y * (1.0f + erff(y * 0.70710678118654752f));
    }
    __syncthreads();

    if (tid < 128) {
        float g = c2b[k];
#pragma unroll
        for (int r = 0; r < R; r++) g += c1_s[r] * c2w[r*K + k];
        g_gate[b*K + k] = 1.0f / (1.0f + expf(-g));
    }
}

// ---------------- K56: fused H-GEMM + gated GCN + LN (f32x2, 2 CTA/SM) ------
// Phase A: thread = (kq 0..31 -> 4 k, vh 0..1 -> 13 v (padded), ta 0..3).
//          acc[13][2] ULL. LDS/FFMA2 = 0.29 (was 0.54).
// Phase B: thread = (kp 0..63 -> k-pair, ug 0..3 -> disjoint u-range).
//          z[4][7] ULL covers all 4 t; a-loads shared across t. ratio 0.39.
#define TT 4
__global__ void __launch_bounds__(256, 2) k56_fused(
        const float* __restrict__ x,
        const float* __restrict__ xiw, const float* __restrict__ xib,
        const float* __restrict__ l2w, const float* __restrict__ l2b,
        float* __restrict__ out) {
    extern __shared__ float sm6[];
    float* Hs   = sm6;                 // 100*128 = 12800
    float* xs2  = Hs  + 12800;         // 104*32  = 3328 (dup, 26 rows per ta)
    float* ws   = xs2 + 3328;          // 16*128  = 2048
    float* As0  = ws  + 2048;          // 3200
    float* As1  = As0 + 3200;          // 3200
    float* mu_s = As1 + 3200;          // 100
    float* rs_s = mu_s + 100;          // 100 (+pad)

    int b  = blockIdx.x >> 5;
    int tt = blockIdx.x & 31;
    int tid  = threadIdx.x;

    // ---------- Phase A ------------------------------------------------------
    int kq = tid & 31;                 // k quad: k0..k0+3
    int vh = (tid >> 5) & 1;           // v half
    int ta = tid >> 6;                 // t group 0..3
    int k0 = kq*4;
    int vbase = vh*13;                 // 0 or 13 (row 25 is zero-padded dummy)

    const size_t xbase = ((size_t)(b*T + tt*TT))*V*C;  // 100 contiguous rows
    unsigned int ws_sa = smem_u32(ws);

    // zero the 4 dummy rows (ta*26 + 25)
    for (int lin = tid; lin < 128; lin += 256) {
        int g = lin >> 5, c = lin & 31;
        xs2[(g*26 + 25)*32 + c] = 0.f;
    }

    unsigned long long acc[13][2];
#pragma unroll
    for (int v = 0; v < 13; v++) { acc[v][0] = 0ull; acc[v][1] = 0ull; }

    for (int cc = 0; cc < C; cc += 16) {
        // w chunk via cp.async: 2048 floats = 512 x 16B chunks
        for (int lin = tid; lin < 512; lin += 256) {
            int c = lin >> 5, f4 = (lin & 31) << 2;
            CP_ASYNC16(ws_sa + (c*128 + f4)*4, &xiw[(cc + c)*K + f4]);
        }
        CP_COMMIT();
        // x chunk duplicated into padded slots
        for (int lin = tid; lin < 400; lin += 256) {
            int r = lin >> 2, c4 = (lin & 3) << 2;
            float4 xv = *(const float4*)&x[xbase + (size_t)r*C + cc + c4];
            int slot = (r/25)*26 + (r%25);
            float* d = &xs2[slot*32 + 2*c4];
            *(float2*)&d[0] = make_float2(xv.x, xv.x);
            *(float2*)&d[2] = make_float2(xv.y, xv.y);
            *(float2*)&d[4] = make_float2(xv.z, xv.z);
            *(float2*)&d[6] = make_float2(xv.w, xv.w);
        }
        CP_WAIT0();
        __syncthreads();
#pragma unroll
        for (int cg = 0; cg < 8; cg++) {
            int c0 = cg*2;
            ulonglong2 w0 = *(const ulonglong2*)&ws[c0*128 + k0];
            ulonglong2 w1 = *(const ulonglong2*)&ws[(c0+1)*128 + k0];
            const float* xr = &xs2[(ta*26 + vbase)*32 + 2*c0];
#pragma unroll
            for (int v = 0; v < 13; v++) {
                ulonglong2 xp = *(const ulonglong2*)&xr[v*32];
                acc[v][0] = fma2(xp.x, w0.x, acc[v][0]);
                acc[v][1] = fma2(xp.x, w0.y, acc[v][1]);
                acc[v][0] = fma2(xp.y, w1.x, acc[v][0]);
                acc[v][1] = fma2(xp.y, w1.y, acc[v][1]);
            }
        }
        __syncthreads();
    }

    // write H tile (+bias) to smem; guard dummy row
    {
        float4 b4 = *(const float4*)&xib[k0];
#pragma unroll
        for (int v = 0; v < 13; v++) {
            int row = vbase + v;
            if (row < V) {
                float f0,f1,f2,f3;
                unpack2(acc[v][0], f0, f1);
                unpack2(acc[v][1], f2, f3);
                float4 o = make_float4(f0+b4.x, f1+b4.y, f2+b4.z, f3+b4.w);
                *(float4*)&Hs[(ta*V + row)*K + k0] = o;
            }
        }
    }

    // ---------- Phase B: Z = gate * (A_tilde . H), LayerNorm over k ----------
    int kp = tid & 63;                 // k-pair index (k = 2*kp, 2*kp+1)
    int ug = tid >> 6;                 // u group 0..3 (disjoint outputs)
    int ub = (ug == 0) ? 0 : (7 + 6*(ug-1));   // 0,7,13,19
    int uc = (ug == 0) ? 7 : 6;

    const float* Ab = g_Atil + (size_t)b*V*V*K;
    unsigned int a_sa[2];
    a_sa[0] = smem_u32(As0);
    a_sa[1] = smem_u32(As1);

    // prologue: stage v=0 into As0: 3200 floats = 800 x 16B chunks
    for (int lin = tid; lin < 800; lin += 256) {
        int u = lin >> 5, f4 = (lin & 31) << 2;
        CP_ASYNC16(a_sa[0] + (u*K + f4)*4, &Ab[((size_t)u*V + 0)*K + f4]);
    }
    CP_COMMIT();
    CP_WAIT0();
    __syncthreads();

    unsigned long long z[4][7];
#pragma unroll
    for (int t = 0; t < 4; t++)
#pragma unroll
        for (int i = 0; i < 7; i++) z[t][i] = 0ull;

    for (int v = 0; v < V; v++) {
        const float* cur = (v & 1) ? As1 : As0;
        unsigned int nxt_sa = a_sa[(v & 1) ^ 1];
        if (v + 1 < V) {
            for (int lin = tid; lin < 800; lin += 256) {
                int u = lin >> 5, f4 = (lin & 31) << 2;
                CP_ASYNC16(nxt_sa + (u*K + f4)*4, &Ab[((size_t)u*V + (v+1))*K + f4]);
            }
            CP_COMMIT();
        }
        unsigned long long h0 = *(const unsigned long long*)&Hs[(0*V + v)*K + 2*kp];
        unsigned long long h1 = *(const unsigned long long*)&Hs[(1*V + v)*K + 2*kp];
        unsigned long long h2 = *(const unsigned long long*)&Hs[(2*V + v)*K + 2*kp];
        unsigned long long h3 = *(const unsigned long long*)&Hs[(3*V + v)*K + 2*kp];
#pragma unroll
        for (int i = 0; i < 7; i++) {
            unsigned long long a = *(const unsigned long long*)&cur[(ub+i)*K + 2*kp];
            z[0][i] = fma2(h0, a, z[0][i]);
            z[1][i] = fma2(h1, a, z[1][i]);
            z[2][i] = fma2(h2, a, z[2][i]);
            z[3][i] = fma2(h3, a, z[3][i]);
        }
        CP_WAIT0();
        __syncthreads();
    }

    float2 gk = *(const float2*)&g_gate[b*K + 2*kp];
#pragma unroll
    for (int t = 0; t < 4; t++)
#pragma unroll
        for (int i = 0; i < 7; i++) {
            if (i < uc) {
                float zl, zh;
                unpack2(z[t][i], zl, zh);
                *(float2*)&Hs[(t*V + ub + i)*K + 2*kp] =
                    make_float2(zl * gk.x, zh * gk.y);
            }
        }
    __syncthreads();

    // LayerNorm stats (rotated k-scan: conflict-free)
    for (int p = tid; p < TT*V; p += 256) {
        float s = 0.f, s2 = 0.f;
        for (int kk = 0; kk < K; kk++) {
            int k = (kk + p) & 127;
            float val = Hs[p*K + k];
            s += val; s2 += val*val;
        }
        float m = s * (1.0f/K);
        float var = s2 * (1.0f/K) - m*m;
        mu_s[p] = m;
        rs_s[p] = rsqrtf(var + 1e-5f);
    }
    __syncthreads();

    const size_t obase = ((size_t)(b*T + tt*TT))*V*K;
    for (int lin = tid; lin < TT*V*K; lin += 256) {
        int r = lin >> 7, kk = lin & 127;
        float val = (Hs[lin] - mu_s[r]) * rs_s[r];
        out[obase + lin] = val * l2w[kk] + l2b[kk];
    }
}

// ---------------- launch ----------------------------------------------------
extern "C" void kernel_launch(void* const* d_in, const int* in_sizes, int n_in,
                              void* d_out, int out_size) {
    const float* x    = (const float*)d_in[0];
    const float* A    = (const float*)d_in[1];
    const float* lam  = (const float*)d_in[2];
    const float* phiw = (const float*)d_in[3];
    const float* phib = (const float*)d_in[4];
    const float* thw  = (const float*)d_in[5];
    const float* thb  = (const float*)d_in[6];
    const float* kapw = (const float*)d_in[7];
    const float* kapb = (const float*)d_in[8];
    const float* xiw  = (const float*)d_in[9];
    const float* xib  = (const float*)d_in[10];
    const float* qw   = (const float*)d_in[11];
    const float* qb   = (const float*)d_in[12];
    const float* kw   = (const float*)d_in[13];
    const float* kb   = (const float*)d_in[14];
    const float* c1w  = (const float*)d_in[15];
    const float* c1b  = (const float*)d_in[16];
    const float* l1w  = (const float*)d_in[17];
    const float* l1b  = (const float*)d_in[18];
    const float* c2w  = (const float*)d_in[19];
    const float* c2b  = (const float*)d_in[20];
    const float* l2w  = (const float*)d_in[21];
    const float* l2b  = (const float*)d_in[22];
    float* out = (float*)d_out;

    size_t sm2  = (size_t)(3200 + 16384) * 4;
    size_t sm3  = (size_t)(16384 + 32*FPAD) * 4;
    size_t sm4  = (size_t)(4*3200 + 2*4096 + 512 + 32) * 4;
    size_t sm56 = (size_t)(12800 + 3328 + 2048 + 3200 + 3200 + 100 + 108) * 4;

    cudaFuncSetAttribute(k2_small,  cudaFuncAttributeMaxDynamicSharedMemorySize, (int)sm2);
    cudaFuncSetAttribute(k3_atilde, cudaFuncAttributeMaxDynamicSharedMemorySize, (int)sm3);
    cudaFuncSetAttribute(k4_gate,   cudaFuncAttributeMaxDynamicSharedMemorySize, (int)sm4);
    cudaFuncSetAttribute(k56_fused, cudaFuncAttributeMaxDynamicSharedMemorySize, (int)sm56);

    k2_small<<<B, 256, sm2>>>(x, phiw, phib, thw, thb, xiw, xib);
    k3_atilde<<<B*20, 256, sm3>>>(A, lam, kapw, kapb);
    k4_gate<<<B, 512, sm4>>>(qw, qb, kw, kb, c1w, c1b, l1w, l1b, c2w, c2b);
    k56_fused<<<B*32, 256, sm56>>>(x, xiw, xib, l2w, l2b, out);
}

// round 15
// speedup vs baseline: 2.1639x; 1.0807x over previous
#include <cuda_runtime.h>
#include <math.h>

#define B 64
#define T 128
#define V 25
#define C 128
#define K 128
#define R 32

// ---------------- scratch (device globals; no allocations allowed) ----------
__device__ float g_xbar[B*V*C];
__device__ float g_phi [B*V*K];
__device__ float g_theta[B*V*K];
__device__ float g_Hbar[B*V*K];
__device__ float g_Atil[B*V*V*K];      // [b][u][v][k]
__device__ float g_gate[B*K];

// f32x2 packed FMA (SASS FFMA2) -- exact fp32, 2x FFMA-pipe rate
__device__ __forceinline__ unsigned long long fma2(unsigned long long a,
                                                   unsigned long long b,
                                                   unsigned long long c) {
    unsigned long long d;
    asm("fma.rn.f32x2 %0, %1, %2, %3;" : "=l"(d) : "l"(a), "l"(b), "l"(c));
    return d;
}
__device__ __forceinline__ void unpack2(unsigned long long p, float& lo, float& hi) {
    asm("mov.b64 {%0,%1}, %2;" : "=f"(lo), "=f"(hi) : "l"(p));
}
__device__ __forceinline__ unsigned int smem_u32(const void* p) {
    unsigned int a;
    asm("{ .reg .u64 t; cvta.to.shared.u64 t, %1; cvt.u32.u64 %0, t; }"
        : "=r"(a) : "l"(p));
    return a;
}
__device__ __forceinline__ float tanh_fast(float v) {
    float r;
    asm("tanh.approx.f32 %0, %1;" : "=f"(r) : "f"(v));
    return r;
}
// cp.async of 16 BYTES (4 floats)
#define CP_ASYNC16(sa, gp) \
    asm volatile("cp.async.ca.shared.global [%0], [%1], 16;" \
                 :: "r"(sa), "l"(gp) : "memory")
#define CP_COMMIT() asm volatile("cp.async.commit_group;" ::: "memory")
#define CP_WAIT0()  asm volatile("cp.async.wait_group 0;" ::: "memory")

// ---------------- K1: xbar = mean_t x  (1600 blocks, coalesced) -------------
__global__ void k1_xbar(const float* __restrict__ x) {
    int bv = blockIdx.x;
    int c  = threadIdx.x;
    int b = bv / V, v = bv % V;
    const float* p = x + ((size_t)(b*T)*V + v)*C + c;
    float acc = 0.f;
#pragma unroll 8
    for (int t = 0; t < T; t++) acc += p[(size_t)t*V*C];
    g_xbar[bv*C + c] = acc * (1.0f/T);
}

// ---------------- K2: phi_x / theta_x / Hbar  (xbar @ W + b) ----------------
__global__ void k2_small(const float* __restrict__ pw, const float* __restrict__ pb,
                         const float* __restrict__ tw, const float* __restrict__ tb,
                         const float* __restrict__ xw, const float* __restrict__ xb2) {
    extern __shared__ float sm2[];
    float* xb_s = sm2;            // 3200
    float* W_s  = sm2 + 3200;     // 16384
    int b = blockIdx.x, tid = threadIdx.x;
    for (int lin = tid; lin < V*C; lin += 256) xb_s[lin] = g_xbar[b*V*C + lin];

    const float* Wp[3] = {pw, tw, xw};
    const float* Bp[3] = {pb, tb, xb2};
    float* Op[3];
    Op[0] = g_phi; Op[1] = g_theta; Op[2] = g_Hbar;

    for (int w = 0; w < 3; w++) {
        for (int lin = tid; lin < C*K; lin += 256) W_s[lin] = Wp[w][lin];
        __syncthreads();
        for (int task = tid; task < V*(K/4); task += 256) {
            int v  = task >> 5;
            int k4 = (task & 31) << 2;
            float4 acc = *(const float4*)&Bp[w][k4];
            for (int c = 0; c < C; c++) {
                float a = xb_s[v*C + c];
                float4 wv = *(const float4*)&W_s[c*K + k4];
                acc.x += a*wv.x; acc.y += a*wv.y; acc.z += a*wv.z; acc.w += a*wv.w;
            }
            *(float4*)&Op[w][b*V*K + v*K + k4] = acc;
        }
        __syncthreads();
    }
}

// ---------------- K3: A_tilde (tanh.approx) ---------------------------------
#define PAIRS_PER_BLK 32
#define FPAD 132
__global__ void k3_atilde(const float* __restrict__ A, const float* __restrict__ lam_p,
                          const float* __restrict__ kw, const float* __restrict__ kb) {
    extern __shared__ float sm3[];
    float* kap_s = sm3;
    float* F_s   = sm3 + C*K;
    int b = blockIdx.x / 20;
    int chunk = blockIdx.x % 20;
    int tid = threadIdx.x;

    for (int lin = tid; lin < K*K; lin += 256) kap_s[lin] = kw[lin];

    for (int idx = tid; idx < PAIRS_PER_BLK*K; idx += 256) {
        int p = idx >> 7, m = idx & 127;
        int pair = chunk*PAIRS_PER_BLK + p;
        float f = 0.f;
        if (pair < V*V) {
            int i = pair / V, j = pair % V;
            f = tanh_fast(g_phi[(b*V+i)*K + m] - g_theta[(b*V+j)*K + m]);
        }
        F_s[p*FPAD + m] = f;
    }
    __syncthreads();

    int wid = tid >> 5, lane = tid & 31;
    int k0 = wid * 16;
    int pair = chunk*PAIRS_PER_BLK + lane;
    if (pair >= V*V) return;

    float acc[16];
#pragma unroll
    for (int q = 0; q < 16; q++) acc[q] = 0.f;

    for (int m = 0; m < K; m += 4) {
        float4 f4 = *(const float4*)&F_s[lane*FPAD + m];
#pragma unroll
        for (int g = 0; g < 4; g++) {
            float4 r0 = *(const float4*)&kap_s[(m+0)*K + k0 + g*4];
            float4 r1 = *(const float4*)&kap_s[(m+1)*K + k0 + g*4];
            float4 r2 = *(const float4*)&kap_s[(m+2)*K + k0 + g*4];
            float4 r3 = *(const float4*)&kap_s[(m+3)*K + k0 + g*4];
            acc[g*4+0] += f4.x*r0.x + f4.y*r1.x + f4.z*r2.x + f4.w*r3.x;
            acc[g*4+1] += f4.x*r0.y + f4.y*r1.y + f4.z*r2.y + f4.w*r3.y;
            acc[g*4+2] += f4.x*r0.z + f4.y*r1.z + f4.z*r2.z + f4.w*r3.z;
            acc[g*4+3] += f4.x*r0.w + f4.y*r1.w + f4.z*r2.w + f4.w*r3.w;
        }
    }

    float lamv = *lam_p;
    int i = pair / V, j = pair % V;
    int outbase = ((b*V + i)*V + j)*K + k0;
#pragma unroll
    for (int g = 0; g < 4; g++) {
        float4 r;
        int kk = k0 + g*4;
        r.x = A[((kk+0)*V + i)*V + j] + lamv*(acc[g*4+0] + kb[kk+0]);
        r.y = A[((kk+1)*V + i)*V + j] + lamv*(acc[g*4+1] + kb[kk+1]);
        r.z = A[((kk+2)*V + i)*V + j] + lamv*(acc[g*4+2] + kb[kk+2]);
        r.w = A[((kk+3)*V + i)*V + j] + lamv*(acc[g*4+3] + kb[kk+3]);
        *(float4*)&g_Atil[outbase + g*4] = r;
    }
}

// ---------------- K4: gate[b][k] --------------------------------------------
__global__ void __launch_bounds__(512) k4_gate(
        const float* __restrict__ qw, const float* __restrict__ qb,
        const float* __restrict__ kw, const float* __restrict__ kb,
        const float* __restrict__ c1w, const float* __restrict__ c1b,
        const float* __restrict__ l1w, const float* __restrict__ l1b,
        const float* __restrict__ c2w, const float* __restrict__ c2b) {
    extern __shared__ float sm4[];
    float* Hb_s = sm4;
    float* Zb_s = Hb_s + 3200;
    float* XQ_s = Zb_s + 3200;
    float* XK_s = XQ_s + 3200;
    float* qw_s = XK_s + 3200;
    float* kw_s = qw_s + 4096;
    float* ca_s = kw_s + 4096;
    float* c1_s = ca_s + 512;

    int b = blockIdx.x, tid = threadIdx.x;
    int k = tid & 127, uh = tid >> 7;
    for (int lin = tid; lin < V*K; lin += 512) Hb_s[lin] = g_Hbar[b*V*K + lin];
    __syncthreads();

    int u_lo = (uh == 0) ? 0 : (7 + 6*(uh-1));
    int nu   = (uh == 0) ? 7 : 6;

    for (int ui = 0; ui < nu; ui++) {
        int u = u_lo + ui;
        float acc = 0.f;
        const float* ap = g_Atil + ((size_t)(b*V + u)*V)*K + k;
#pragma unroll
        for (int v = 0; v < V; v++) acc += ap[v*K] * Hb_s[v*K + k];
        Zb_s[u*K + k] = acc;
    }
    __syncthreads();

    float accq[7], acck[7];
    for (int ui = 0; ui < nu; ui++) { accq[ui] = qb[k]; acck[ui] = kb[k]; }
    for (int mc = 0; mc < K; mc += 32) {
        for (int lin = tid; lin < 32*128; lin += 512) {
            int mm = lin >> 7, kk = lin & 127;
            qw_s[lin] = qw[(mc + mm)*K + kk];
            kw_s[lin] = kw[(mc + mm)*K + kk];
        }
        __syncthreads();
        for (int ui = 0; ui < nu; ui++) {
            int u = u_lo + ui;
            float aq = accq[ui], ak = acck[ui];
#pragma unroll
            for (int mm = 0; mm < 32; mm++) {
                float z = Zb_s[u*K + mc + mm];
                aq += z * qw_s[mm*128 + k];
                ak += z * kw_s[mm*128 + k];
            }
            accq[ui] = aq; acck[ui] = ak;
        }
        __syncthreads();
    }
    for (int ui = 0; ui < nu; ui++) {
        XQ_s[(u_lo+ui)*K + k] = accq[ui];
        XK_s[(u_lo+ui)*K + k] = acck[ui];
    }
    __syncthreads();

    const float inv_scale = 1.0f / sqrtf((float)T);
    float ca = 0.f;
    for (int ui = 0; ui < nu; ui++) {
        int u = u_lo + ui;
        float xq = XQ_s[u*K + k];
        float mx = -1e30f;
#pragma unroll
        for (int v = 0; v < V; v++) {
            float s = xq * XK_s[v*K + k] * inv_scale;
            mx = fmaxf(mx, s);
        }
        float den = 0.f, num = 0.f;
#pragma unroll
        for (int v = 0; v < V; v++) {
            float s = xq * XK_s[v*K + k] * inv_scale;
            float e = expf(s - mx);
            den += e;
            num += e * Hb_s[v*K + k];
        }
        ca += num / den;
    }
    ca_s[tid] = ca;
    __syncthreads();
    if (tid < 128)
        ca_s[tid] = (ca_s[tid] + ca_s[tid+128] + ca_s[tid+256] + ca_s[tid+384]) * (1.0f/V);
    __syncthreads();

    if (tid < R) {
        float t = c1b[tid];
        for (int kk = 0; kk < K; kk++) t += ca_s[kk] * c1w[kk*R + tid];
        float mu = t;
#pragma unroll
        for (int o = 16; o > 0; o >>= 1) mu += __shfl_xor_sync(0xffffffffu, mu, o);
        mu *= (1.0f/R);
        float d = t - mu;
        float var = d*d;
#pragma unroll
        for (int o = 16; o > 0; o >>= 1) var += __shfl_xor_sync(0xffffffffu, var, o);
        var *= (1.0f/R);
        float y = d * rsqrtf(var + 1e-5f) * l1w[tid] + l1b[tid];
        c1_s[tid] = 0.5f * y * (1.0f + erff(y * 0.70710678118654752f));
    }
    __syncthreads();

    if (tid < 128) {
        float g = c2b[k];
#pragma unroll
        for (int r = 0; r < R; r++) g += c1_s[r] * c2w[r*K + k];
        g_gate[b*K + k] = 1.0f / (1.0f + expf(-g));
    }
}

// ---------------- K56: fused H-GEMM + gated GCN + LN (f32x2, 2 CTA/SM) ------
// Phase A: thread = (kq 0..31 -> 4 k, vh 0..1 -> 13 v (padded), ta 0..3).
// Phase B: thread = (kp 0..63 -> k-pair, ug 0..3 -> disjoint u-range).
#define TT 4
__global__ void __launch_bounds__(256, 2) k56_fused(
        const float* __restrict__ x,
        const float* __restrict__ xiw, const float* __restrict__ xib,
        const float* __restrict__ l2w, const float* __restrict__ l2b,
        float* __restrict__ out) {
    extern __shared__ float sm6[];
    float* Hs   = sm6;                 // 100*128 = 12800
    float* xs2  = Hs  + 12800;         // 104*32  = 3328 (dup, 26 rows per ta)
    float* ws   = xs2 + 3328;          // 16*128  = 2048
    float* As0  = ws  + 2048;          // 3200
    float* As1  = As0 + 3200;          // 3200
    float* mu_s = As1 + 3200;          // 100
    float* rs_s = mu_s + 100;          // 100 (+pad)

    int b  = blockIdx.x >> 5;
    int tt = blockIdx.x & 31;
    int tid  = threadIdx.x;

    // ---------- Phase A ------------------------------------------------------
    int kq = tid & 31;                 // k quad: k0..k0+3
    int vh = (tid >> 5) & 1;           // v half
    int ta = tid >> 6;                 // t group 0..3
    int k0 = kq*4;
    int vbase = vh*13;                 // 0 or 13 (row 25 is zero-padded dummy)

    const size_t xbase = ((size_t)(b*T + tt*TT))*V*C;  // 100 contiguous rows
    unsigned int ws_sa = smem_u32(ws);

    // zero the 4 dummy rows (ta*26 + 25)
    for (int lin = tid; lin < 128; lin += 256) {
        int g = lin >> 5, c = lin & 31;
        xs2[(g*26 + 25)*32 + c] = 0.f;
    }

    unsigned long long acc[13][2];
#pragma unroll
    for (int v = 0; v < 13; v++) { acc[v][0] = 0ull; acc[v][1] = 0ull; }

    for (int cc = 0; cc < C; cc += 16) {
        // w chunk via cp.async: 2048 floats = 512 x 16B chunks
        for (int lin = tid; lin < 512; lin += 256) {
            int c = lin >> 5, f4 = (lin & 31) << 2;
            CP_ASYNC16(ws_sa + (c*128 + f4)*4, &xiw[(cc + c)*K + f4]);
        }
        CP_COMMIT();
        // x chunk duplicated into padded slots
        for (int lin = tid; lin < 400; lin += 256) {
            int r = lin >> 2, c4 = (lin & 3) << 2;
            float4 xv = *(const float4*)&x[xbase + (size_t)r*C + cc + c4];
            int slot = (r/25)*26 + (r%25);
            float* d = &xs2[slot*32 + 2*c4];
            *(float2*)&d[0] = make_float2(xv.x, xv.x);
            *(float2*)&d[2] = make_float2(xv.y, xv.y);
            *(float2*)&d[4] = make_float2(xv.z, xv.z);
            *(float2*)&d[6] = make_float2(xv.w, xv.w);
        }
        CP_WAIT0();
        __syncthreads();
#pragma unroll
        for (int cg = 0; cg < 8; cg++) {
            int c0 = cg*2;
            ulonglong2 w0 = *(const ulonglong2*)&ws[c0*128 + k0];
            ulonglong2 w1 = *(const ulonglong2*)&ws[(c0+1)*128 + k0];
            const float* xr = &xs2[(ta*26 + vbase)*32 + 2*c0];
#pragma unroll
            for (int v = 0; v < 13; v++) {
                ulonglong2 xp = *(const ulonglong2*)&xr[v*32];
                acc[v][0] = fma2(xp.x, w0.x, acc[v][0]);
                acc[v][1] = fma2(xp.x, w0.y, acc[v][1]);
                acc[v][0] = fma2(xp.y, w1.x, acc[v][0]);
                acc[v][1] = fma2(xp.y, w1.y, acc[v][1]);
            }
        }
        __syncthreads();
    }

    // write H tile (+bias) to smem; guard dummy row
    {
        float4 b4 = *(const float4*)&xib[k0];
#pragma unroll
        for (int v = 0; v < 13; v++) {
            int row = vbase + v;
            if (row < V) {
                float f0,f1,f2,f3;
                unpack2(acc[v][0], f0, f1);
                unpack2(acc[v][1], f2, f3);
                float4 o = make_float4(f0+b4.x, f1+b4.y, f2+b4.z, f3+b4.w);
                *(float4*)&Hs[(ta*V + row)*K + k0] = o;
            }
        }
    }

    // ---------- Phase B: Z = gate * (A_tilde . H), LayerNorm over k ----------
    int kp = tid & 63;                 // k-pair index (k = 2*kp, 2*kp+1)
    int ug = tid >> 6;                 // u group 0..3 (disjoint outputs)
    int ub = (ug == 0) ? 0 : (7 + 6*(ug-1));   // 0,7,13,19
    int uc = (ug == 0) ? 7 : 6;

    const float* Ab = g_Atil + (size_t)b*V*V*K;
    unsigned int a_sa[2];
    a_sa[0] = smem_u32(As0);
    a_sa[1] = smem_u32(As1);

    // prologue: stage v=0 into As0: 3200 floats = 800 x 16B chunks
    for (int lin = tid; lin < 800; lin += 256) {
        int u = lin >> 5, f4 = (lin & 31) << 2;
        CP_ASYNC16(a_sa[0] + (u*K + f4)*4, &Ab[((size_t)u*V + 0)*K + f4]);
    }
    CP_COMMIT();
    CP_WAIT0();
    __syncthreads();

    unsigned long long z[4][7];
#pragma unroll
    for (int t = 0; t < 4; t++)
#pragma unroll
        for (int i = 0; i < 7; i++) z[t][i] = 0ull;

    for (int v = 0; v < V; v++) {
        const float* cur = (v & 1) ? As1 : As0;
        unsigned int nxt_sa = a_sa[(v & 1) ^ 1];
        if (v + 1 < V) {
            for (int lin = tid; lin < 800; lin += 256) {
                int u = lin >> 5, f4 = (lin & 31) << 2;
                CP_ASYNC16(nxt_sa + (u*K + f4)*4, &Ab[((size_t)u*V + (v+1))*K + f4]);
            }
            CP_COMMIT();
        }
        unsigned long long h0 = *(const unsigned long long*)&Hs[(0*V + v)*K + 2*kp];
        unsigned long long h1 = *(const unsigned long long*)&Hs[(1*V + v)*K + 2*kp];
        unsigned long long h2 = *(const unsigned long long*)&Hs[(2*V + v)*K + 2*kp];
        unsigned long long h3 = *(const unsigned long long*)&Hs[(3*V + v)*K + 2*kp];
#pragma unroll
        for (int i = 0; i < 7; i++) {
            unsigned long long a = *(const unsigned long long*)&cur[(ub+i)*K + 2*kp];
            z[0][i] = fma2(h0, a, z[0][i]);
            z[1][i] = fma2(h1, a, z[1][i]);
            z[2][i] = fma2(h2, a, z[2][i]);
            z[3][i] = fma2(h3, a, z[3][i]);
        }
        CP_WAIT0();
        __syncthreads();
    }

    float2 gk = *(const float2*)&g_gate[b*K + 2*kp];
#pragma unroll
    for (int t = 0; t < 4; t++)
#pragma unroll
        for (int i = 0; i < 7; i++) {
            if (i < uc) {
                float zl, zh;
                unpack2(z[t][i], zl, zh);
                *(float2*)&Hs[(t*V + ub + i)*K + 2*kp] =
                    make_float2(zl * gk.x, zh * gk.y);
            }
        }
    __syncthreads();

    // LayerNorm stats (rotated k-scan: conflict-free)
    for (int p = tid; p < TT*V; p += 256) {
        float s = 0.f, s2 = 0.f;
        for (int kk = 0; kk < K; kk++) {
            int k = (kk + p) & 127;
            float val = Hs[p*K + k];
            s += val; s2 += val*val;
        }
        float m = s * (1.0f/K);
        float var = s2 * (1.0f/K) - m*m;
        mu_s[p] = m;
        rs_s[p] = rsqrtf(var + 1e-5f);
    }
    __syncthreads();

    const size_t obase = ((size_t)(b*T + tt*TT))*V*K;
    for (int lin = tid; lin < TT*V*K; lin += 256) {
        int r = lin >> 7, kk = lin & 127;
        float val = (Hs[lin] - mu_s[r]) * rs_s[r];
        out[obase + lin] = val * l2w[kk] + l2b[kk];
    }
}

// ---------------- launch ----------------------------------------------------
extern "C" void kernel_launch(void* const* d_in, const int* in_sizes, int n_in,
                              void* d_out, int out_size) {
    const float* x    = (const float*)d_in[0];
    const float* A    = (const float*)d_in[1];
    const float* lam  = (const float*)d_in[2];
    const float* phiw = (const float*)d_in[3];
    const float* phib = (const float*)d_in[4];
    const float* thw  = (const float*)d_in[5];
    const float* thb  = (const float*)d_in[6];
    const float* kapw = (const float*)d_in[7];
    const float* kapb = (const float*)d_in[8];
    const float* xiw  = (const float*)d_in[9];
    const float* xib  = (const float*)d_in[10];
    const float* qw   = (const float*)d_in[11];
    const float* qb   = (const float*)d_in[12];
    const float* kw   = (const float*)d_in[13];
    const float* kb   = (const float*)d_in[14];
    const float* c1w  = (const float*)d_in[15];
    const float* c1b  = (const float*)d_in[16];
    const float* l1w  = (const float*)d_in[17];
    const float* l1b  = (const float*)d_in[18];
    const float* c2w  = (const float*)d_in[19];
    const float* c2b  = (const float*)d_in[20];
    const float* l2w  = (const float*)d_in[21];
    const float* l2b  = (const float*)d_in[22];
    float* out = (float*)d_out;

    size_t sm2  = (size_t)(3200 + 16384) * 4;
    size_t sm3  = (size_t)(16384 + 32*FPAD) * 4;
    size_t sm4  = (size_t)(4*3200 + 2*4096 + 512 + 32) * 4;
    size_t sm56 = (size_t)(12800 + 3328 + 2048 + 3200 + 3200 + 100 + 108) * 4;

    cudaFuncSetAttribute(k2_small,  cudaFuncAttributeMaxDynamicSharedMemorySize, (int)sm2);
    cudaFuncSetAttribute(k3_atilde, cudaFuncAttributeMaxDynamicSharedMemorySize, (int)sm3);
    cudaFuncSetAttribute(k4_gate,   cudaFuncAttributeMaxDynamicSharedMemorySize, (int)sm4);
    cudaFuncSetAttribute(k56_fused, cudaFuncAttributeMaxDynamicSharedMemorySize, (int)sm56);

    k1_xbar<<<B*V, 128>>>(x);
    k2_small<<<B, 256, sm2>>>(phiw, phib, thw, thb, xiw, xib);
    k3_atilde<<<B*20, 256, sm3>>>(A, lam, kapw, kapb);
    k4_gate<<<B, 512, sm4>>>(qw, qb, kw, kb, c1w, c1b, l1w, l1b, c2w, c2b);
    k56_fused<<<B*32, 256, sm56>>>(x, xiw, xib, l2w, l2b, out);
}

// round 16
// speedup vs baseline: 2.3230x; 1.0736x over previous
#include <cuda_runtime.h>
#include <math.h>

#define B 64
#define T 128
#define V 25
#define C 128
#define K 128
#define R 32

// ---------------- scratch (device globals; no allocations allowed) ----------
__device__ float g_xbar[B*V*C];
__device__ float g_phi [B*V*K];
__device__ float g_theta[B*V*K];
__device__ float g_Hbar[B*V*K];
__device__ float g_Atil[B*V*V*K];      // [b][u][v][k]
__device__ float g_gate[B*K];

// f32x2 packed FMA (SASS FFMA2) -- exact fp32, 2x FFMA-pipe rate
__device__ __forceinline__ unsigned long long fma2(unsigned long long a,
                                                   unsigned long long b,
                                                   unsigned long long c) {
    unsigned long long d;
    asm("fma.rn.f32x2 %0, %1, %2, %3;" : "=l"(d) : "l"(a), "l"(b), "l"(c));
    return d;
}
__device__ __forceinline__ void unpack2(unsigned long long p, float& lo, float& hi) {
    asm("mov.b64 {%0,%1}, %2;" : "=f"(lo), "=f"(hi) : "l"(p));
}
__device__ __forceinline__ unsigned long long pack2(float v) {
    unsigned long long r;
    asm("mov.b64 %0, {%1,%1};" : "=l"(r) : "f"(v));
    return r;
}
__device__ __forceinline__ unsigned int smem_u32(const void* p) {
    unsigned int a;
    asm("{ .reg .u64 t; cvta.to.shared.u64 t, %1; cvt.u32.u64 %0, t; }"
        : "=r"(a) : "l"(p));
    return a;
}
__device__ __forceinline__ float tanh_fast(float v) {
    float r;
    asm("tanh.approx.f32 %0, %1;" : "=f"(r) : "f"(v));
    return r;
}
// cp.async of 16 BYTES (4 floats)
#define CP_ASYNC16(sa, gp) \
    asm volatile("cp.async.ca.shared.global [%0], [%1], 16;" \
                 :: "r"(sa), "l"(gp) : "memory")
#define CP_COMMIT() asm volatile("cp.async.commit_group;" ::: "memory")
#define CP_WAIT0()  asm volatile("cp.async.wait_group 0;" ::: "memory")

// ---------------- K1: xbar = mean_t x  (1600 blocks, coalesced) -------------
__global__ void k1_xbar(const float* __restrict__ x) {
    int bv = blockIdx.x;
    int c  = threadIdx.x;
    int b = bv / V, v = bv % V;
    const float* p = x + ((size_t)(b*T)*V + v)*C + c;
    float acc = 0.f;
#pragma unroll 8
    for (int t = 0; t < T; t++) acc += p[(size_t)t*V*C];
    g_xbar[bv*C + c] = acc * (1.0f/T);
}

// ---------------- K2: phi_x / theta_x / Hbar  (xbar @ W + b) ----------------
__global__ void k2_small(const float* __restrict__ pw, const float* __restrict__ pb,
                         const float* __restrict__ tw, const float* __restrict__ tb,
                         const float* __restrict__ xw, const float* __restrict__ xb2) {
    extern __shared__ float sm2[];
    float* xb_s = sm2;            // 3200
    float* W_s  = sm2 + 3200;     // 16384
    int b = blockIdx.x, tid = threadIdx.x;
    for (int lin = tid; lin < V*C; lin += 256) xb_s[lin] = g_xbar[b*V*C + lin];

    const float* Wp[3] = {pw, tw, xw};
    const float* Bp[3] = {pb, tb, xb2};
    float* Op[3];
    Op[0] = g_phi; Op[1] = g_theta; Op[2] = g_Hbar;

    for (int w = 0; w < 3; w++) {
        for (int lin = tid; lin < C*K; lin += 256) W_s[lin] = Wp[w][lin];
        __syncthreads();
        for (int task = tid; task < V*(K/4); task += 256) {
            int v  = task >> 5;
            int k4 = (task & 31) << 2;
            float4 acc = *(const float4*)&Bp[w][k4];
            for (int c = 0; c < C; c++) {
                float a = xb_s[v*C + c];
                float4 wv = *(const float4*)&W_s[c*K + k4];
                acc.x += a*wv.x; acc.y += a*wv.y; acc.z += a*wv.z; acc.w += a*wv.w;
            }
            *(float4*)&Op[w][b*V*K + v*K + k4] = acc;
        }
        __syncthreads();
    }
}

// ---------------- K3: A_tilde  (f32x2 GEMM: F[64p x 128m] @ kappa[128m x 128k])
// grid = 64 b x 10 pair-chunks. 256 threads, 2 CTA/SM.
// thread = (kq 0..31 -> 4 k, pg 0..7 -> 8 pairs). acc[8][2] ULL.
__global__ void __launch_bounds__(256, 2) k3_atilde(
        const float* __restrict__ A, const float* __restrict__ lam_p,
        const float* __restrict__ kw, const float* __restrict__ kb) {
    extern __shared__ float sm3[];
    float* kap_s = sm3;            // 128*128 = 16384
    float* F_s   = sm3 + 16384;    // 64*132  = 8448 (also reused for A slice)
    int b      = blockIdx.x / 10;
    int pchunk = blockIdx.x % 10;
    int tid = threadIdx.x;
    int p0 = pchunk * 64;
    unsigned int kap_sa = smem_u32(kap_s);

    // stage kappa via cp.async: 16384 floats = 4096 x 16B
    for (int lin = tid; lin < 4096; lin += 256) {
        int m = lin >> 5, f4 = (lin & 31) << 2;
        CP_ASYNC16(kap_sa + (m*128 + f4)*4, &kw[m*K + f4]);
    }
    CP_COMMIT();

    // F chunk: 64 pairs x 128 m (coalesced phi/theta reads, tanh.approx)
    for (int lin = tid; lin < 64*128; lin += 256) {
        int p = lin >> 7, m = lin & 127;
        int pair = p0 + p;
        float f = 0.f;
        if (pair < V*V) {
            int i = pair / V, j = pair % V;
            f = tanh_fast(g_phi[(b*V+i)*K + m] - g_theta[(b*V+j)*K + m]);
        }
        F_s[p*132 + m] = f;
    }
    CP_WAIT0();
    __syncthreads();

    int kq = tid & 31;             // k quad -> k0..k0+3
    int pg = tid >> 5;             // pair group: pg*8 .. +7
    int k0 = kq * 4;

    unsigned long long acc[8][2];
#pragma unroll
    for (int p = 0; p < 8; p++) { acc[p][0] = 0ull; acc[p][1] = 0ull; }

    for (int m = 0; m < K; m += 4) {
        ulonglong2 q0 = *(const ulonglong2*)&kap_s[(m+0)*128 + k0];
        ulonglong2 q1 = *(const ulonglong2*)&kap_s[(m+1)*128 + k0];
        ulonglong2 q2 = *(const ulonglong2*)&kap_s[(m+2)*128 + k0];
        ulonglong2 q3 = *(const ulonglong2*)&kap_s[(m+3)*128 + k0];
#pragma unroll
        for (int p = 0; p < 8; p++) {
            float4 f4 = *(const float4*)&F_s[(pg*8 + p)*132 + m];  // broadcast
            unsigned long long f0 = pack2(f4.x);
            unsigned long long f1 = pack2(f4.y);
            unsigned long long f2 = pack2(f4.z);
            unsigned long long f3 = pack2(f4.w);
            acc[p][0] = fma2(f0, q0.x, acc[p][0]);
            acc[p][1] = fma2(f0, q0.y, acc[p][1]);
            acc[p][0] = fma2(f1, q1.x, acc[p][0]);
            acc[p][1] = fma2(f1, q1.y, acc[p][1]);
            acc[p][0] = fma2(f2, q2.x, acc[p][0]);
            acc[p][1] = fma2(f2, q2.y, acc[p][1]);
            acc[p][0] = fma2(f3, q3.x, acc[p][0]);
            acc[p][1] = fma2(f3, q3.y, acc[p][1]);
        }
    }
    __syncthreads();   // done reading F_s; reuse it for the A slice

    // stage A slice [p][k] coalesced: F_s[p*132 + k] = A[k*625 + p0 + p]
    for (int lin = tid; lin < 64*128; lin += 256) {
        int p = lin & 63, k = lin >> 6;
        float av = 0.f;
        if (p0 + p < V*V) av = A[(size_t)k*(V*V) + p0 + p];
        F_s[p*132 + k] = av;
    }
    __syncthreads();

    float lamv = *lam_p;
    float4 kb4 = *(const float4*)&kb[k0];
#pragma unroll
    for (int p = 0; p < 8; p++) {
        int pair = p0 + pg*8 + p;
        if (pair < V*V) {
            int i = pair / V, j = pair % V;
            float r0, r1, r2, r3;
            unpack2(acc[p][0], r0, r1);
            unpack2(acc[p][1], r2, r3);
            float4 a4 = *(const float4*)&F_s[(pg*8 + p)*132 + k0];
            float4 o;
            o.x = a4.x + lamv*(r0 + kb4.x);
            o.y = a4.y + lamv*(r1 + kb4.y);
            o.z = a4.z + lamv*(r2 + kb4.z);
            o.w = a4.w + lamv*(r3 + kb4.w);
            *(float4*)&g_Atil[((size_t)(b*V + i)*V + j)*K + k0] = o;
        }
    }
}

// ---------------- K4: gate[b][k] --------------------------------------------
__global__ void __launch_bounds__(512) k4_gate(
        const float* __restrict__ qw, const float* __restrict__ qb,
        const float* __restrict__ kw, const float* __restrict__ kb,
        const float* __restrict__ c1w, const float* __restrict__ c1b,
        const float* __restrict__ l1w, const float* __restrict__ l1b,
        const float* __restrict__ c2w, const float* __restrict__ c2b) {
    extern __shared__ float sm4[];
    float* Hb_s = sm4;
    float* Zb_s = Hb_s + 3200;
    float* XQ_s = Zb_s + 3200;
    float* XK_s = XQ_s + 3200;
    float* qw_s = XK_s + 3200;
    float* kw_s = qw_s + 4096;
    float* ca_s = kw_s + 4096;
    float* c1_s = ca_s + 512;

    int b = blockIdx.x, tid = threadIdx.x;
    int k = tid & 127, uh = tid >> 7;
    for (int lin = tid; lin < V*K; lin += 512) Hb_s[lin] = g_Hbar[b*V*K + lin];
    __syncthreads();

    int u_lo = (uh == 0) ? 0 : (7 + 6*(uh-1));
    int nu   = (uh == 0) ? 7 : 6;

    for (int ui = 0; ui < nu; ui++) {
        int u = u_lo + ui;
        float acc = 0.f;
        const float* ap = g_Atil + ((size_t)(b*V + u)*V)*K + k;
#pragma unroll
        for (int v = 0; v < V; v++) acc += ap[v*K] * Hb_s[v*K + k];
        Zb_s[u*K + k] = acc;
    }
    __syncthreads();

    float accq[7], acck[7];
    for (int ui = 0; ui < nu; ui++) { accq[ui] = qb[k]; acck[ui] = kb[k]; }
    for (int mc = 0; mc < K; mc += 32) {
        for (int lin = tid; lin < 32*128; lin += 512) {
            int mm = lin >> 7, kk = lin & 127;
            qw_s[lin] = qw[(mc + mm)*K + kk];
            kw_s[lin] = kw[(mc + mm)*K + kk];
        }
        __syncthreads();
        for (int ui = 0; ui < nu; ui++) {
            int u = u_lo + ui;
            float aq = accq[ui], ak = acck[ui];
#pragma unroll
            for (int mm = 0; mm < 32; mm++) {
                float z = Zb_s[u*K + mc + mm];
                aq += z * qw_s[mm*128 + k];
                ak += z * kw_s[mm*128 + k];
            }
            accq[ui] = aq; acck[ui] = ak;
        }
        __syncthreads();
    }
    for (int ui = 0; ui < nu; ui++) {
        XQ_s[(u_lo+ui)*K + k] = accq[ui];
        XK_s[(u_lo+ui)*K + k] = acck[ui];
    }
    __syncthreads();

    const float inv_scale = 1.0f / sqrtf((float)T);
    float ca = 0.f;
    for (int ui = 0; ui < nu; ui++) {
        int u = u_lo + ui;
        float xq = XQ_s[u*K + k];
        float mx = -1e30f;
#pragma unroll
        for (int v = 0; v < V; v++) {
            float s = xq * XK_s[v*K + k] * inv_scale;
            mx = fmaxf(mx, s);
        }
        float den = 0.f, num = 0.f;
#pragma unroll
        for (int v = 0; v < V; v++) {
            float s = xq * XK_s[v*K + k] * inv_scale;
            float e = expf(s - mx);
            den += e;
            num += e * Hb_s[v*K + k];
        }
        ca += num / den;
    }
    ca_s[tid] = ca;
    __syncthreads();
    if (tid < 128)
        ca_s[tid] = (ca_s[tid] + ca_s[tid+128] + ca_s[tid+256] + ca_s[tid+384]) * (1.0f/V);
    __syncthreads();

    if (tid < R) {
        float t = c1b[tid];
        for (int kk = 0; kk < K; kk++) t += ca_s[kk] * c1w[kk*R + tid];
        float mu = t;
#pragma unroll
        for (int o = 16; o > 0; o >>= 1) mu += __shfl_xor_sync(0xffffffffu, mu, o);
        mu *= (1.0f/R);
        float d = t - mu;
        float var = d*d;
#pragma unroll
        for (int o = 16; o > 0; o >>= 1) var += __shfl_xor_sync(0xffffffffu, var, o);
        var *= (1.0f/R);
        float y = d * rsqrtf(var + 1e-5f) * l1w[tid] + l1b[tid];
        c1_s[tid] = 0.5f * y * (1.0f + erff(y * 0.70710678118654752f));
    }
    __syncthreads();

    if (tid < 128) {
        float g = c2b[k];
#pragma unroll
        for (int r = 0; r < R; r++) g += c1_s[r] * c2w[r*K + k];
        g_gate[b*K + k] = 1.0f / (1.0f + expf(-g));
    }
}

// ---------------- K56: fused H-GEMM + gated GCN + LN (f32x2, 2 CTA/SM) ------
// Phase A: thread = (kq 0..31 -> 4 k, vh 0..1 -> 13 v (padded), ta 0..3).
// Phase B: thread = (kp 0..63 -> k-pair, ug 0..3 -> disjoint u-range).
#define TT 4
__global__ void __launch_bounds__(256, 2) k56_fused(
        const float* __restrict__ x,
        const float* __restrict__ xiw, const float* __restrict__ xib,
        const float* __restrict__ l2w, const float* __restrict__ l2b,
        float* __restrict__ out) {
    extern __shared__ float sm6[];
    float* Hs   = sm6;                 // 100*128 = 12800
    float* xs2  = Hs  + 12800;         // 104*32  = 3328 (dup, 26 rows per ta)
    float* ws   = xs2 + 3328;          // 16*128  = 2048
    float* As0  = ws  + 2048;          // 3200
    float* As1  = As0 + 3200;          // 3200
    float* mu_s = As1 + 3200;          // 100
    float* rs_s = mu_s + 100;          // 100 (+pad)

    int b  = blockIdx.x >> 5;
    int tt = blockIdx.x & 31;
    int tid  = threadIdx.x;

    // ---------- Phase A ------------------------------------------------------
    int kq = tid & 31;                 // k quad: k0..k0+3
    int vh = (tid >> 5) & 1;           // v half
    int ta = tid >> 6;                 // t group 0..3
    int k0 = kq*4;
    int vbase = vh*13;                 // 0 or 13 (row 25 is zero-padded dummy)

    const size_t xbase = ((size_t)(b*T + tt*TT))*V*C;  // 100 contiguous rows
    unsigned int ws_sa = smem_u32(ws);

    // zero the 4 dummy rows (ta*26 + 25)
    for (int lin = tid; lin < 128; lin += 256) {
        int g = lin >> 5, c = lin & 31;
        xs2[(g*26 + 25)*32 + c] = 0.f;
    }

    unsigned long long acc[13][2];
#pragma unroll
    for (int v = 0; v < 13; v++) { acc[v][0] = 0ull; acc[v][1] = 0ull; }

    for (int cc = 0; cc < C; cc += 16) {
        // w chunk via cp.async: 2048 floats = 512 x 16B chunks
        for (int lin = tid; lin < 512; lin += 256) {
            int c = lin >> 5, f4 = (lin & 31) << 2;
            CP_ASYNC16(ws_sa + (c*128 + f4)*4, &xiw[(cc + c)*K + f4]);
        }
        CP_COMMIT();
        // x chunk duplicated into padded slots
        for (int lin = tid; lin < 400; lin += 256) {
            int r = lin >> 2, c4 = (lin & 3) << 2;
            float4 xv = *(const float4*)&x[xbase + (size_t)r*C + cc + c4];
            int slot = (r/25)*26 + (r%25);
            float* d = &xs2[slot*32 + 2*c4];
            *(float2*)&d[0] = make_float2(xv.x, xv.x);
            *(float2*)&d[2] = make_float2(xv.y, xv.y);
            *(float2*)&d[4] = make_float2(xv.z, xv.z);
            *(float2*)&d[6] = make_float2(xv.w, xv.w);
        }
        CP_WAIT0();
        __syncthreads();
#pragma unroll
        for (int cg = 0; cg < 8; cg++) {
            int c0 = cg*2;
            ulonglong2 w0 = *(const ulonglong2*)&ws[c0*128 + k0];
            ulonglong2 w1 = *(const ulonglong2*)&ws[(c0+1)*128 + k0];
            const float* xr = &xs2[(ta*26 + vbase)*32 + 2*c0];
#pragma unroll
            for (int v = 0; v < 13; v++) {
                ulonglong2 xp = *(const ulonglong2*)&xr[v*32];
                acc[v][0] = fma2(xp.x, w0.x, acc[v][0]);
                acc[v][1] = fma2(xp.x, w0.y, acc[v][1]);
                acc[v][0] = fma2(xp.y, w1.x, acc[v][0]);
                acc[v][1] = fma2(xp.y, w1.y, acc[v][1]);
            }
        }
        __syncthreads();
    }

    // write H tile (+bias) to smem; guard dummy row
    {
        float4 b4 = *(const float4*)&xib[k0];
#pragma unroll
        for (int v = 0; v < 13; v++) {
            int row = vbase + v;
            if (row < V) {
                float f0,f1,f2,f3;
                unpack2(acc[v][0], f0, f1);
                unpack2(acc[v][1], f2, f3);
                float4 o = make_float4(f0+b4.x, f1+b4.y, f2+b4.z, f3+b4.w);
                *(float4*)&Hs[(ta*V + row)*K + k0] = o;
            }
        }
    }

    // ---------- Phase B: Z = gate * (A_tilde . H), LayerNorm over k ----------
    int kp = tid & 63;                 // k-pair index (k = 2*kp, 2*kp+1)
    int ug = tid >> 6;                 // u group 0..3 (disjoint outputs)
    int ub = (ug == 0) ? 0 : (7 + 6*(ug-1));   // 0,7,13,19
    int uc = (ug == 0) ? 7 : 6;

    const float* Ab = g_Atil + (size_t)b*V*V*K;
    unsigned int a_sa[2];
    a_sa[0] = smem_u32(As0);
    a_sa[1] = smem_u32(As1);

    // prologue: stage v=0 into As0: 3200 floats = 800 x 16B chunks
    for (int lin = tid; lin < 800; lin += 256) {
        int u = lin >> 5, f4 = (lin & 31) << 2;
        CP_ASYNC16(a_sa[0] + (u*K + f4)*4, &Ab[((size_t)u*V + 0)*K + f4]);
    }
    CP_COMMIT();
    CP_WAIT0();
    __syncthreads();

    unsigned long long z[4][7];
#pragma unroll
    for (int t = 0; t < 4; t++)
#pragma unroll
        for (int i = 0; i < 7; i++) z[t][i] = 0ull;

    for (int v = 0; v < V; v++) {
        const float* cur = (v & 1) ? As1 : As0;
        unsigned int nxt_sa = a_sa[(v & 1) ^ 1];
        if (v + 1 < V) {
            for (int lin = tid; lin < 800; lin += 256) {
                int u = lin >> 5, f4 = (lin & 31) << 2;
                CP_ASYNC16(nxt_sa + (u*K + f4)*4, &Ab[((size_t)u*V + (v+1))*K + f4]);
            }
            CP_COMMIT();
        }
        unsigned long long h0 = *(const unsigned long long*)&Hs[(0*V + v)*K + 2*kp];
        unsigned long long h1 = *(const unsigned long long*)&Hs[(1*V + v)*K + 2*kp];
        unsigned long long h2 = *(const unsigned long long*)&Hs[(2*V + v)*K + 2*kp];
        unsigned long long h3 = *(const unsigned long long*)&Hs[(3*V + v)*K + 2*kp];
#pragma unroll
        for (int i = 0; i < 7; i++) {
            unsigned long long a = *(const unsigned long long*)&cur[(ub+i)*K + 2*kp];
            z[0][i] = fma2(h0, a, z[0][i]);
            z[1][i] = fma2(h1, a, z[1][i]);
            z[2][i] = fma2(h2, a, z[2][i]);
            z[3][i] = fma2(h3, a, z[3][i]);
        }
        CP_WAIT0();
        __syncthreads();
    }

    float2 gk = *(const float2*)&g_gate[b*K + 2*kp];
#pragma unroll
    for (int t = 0; t < 4; t++)
#pragma unroll
        for (int i = 0; i < 7; i++) {
            if (i < uc) {
                float zl, zh;
                unpack2(z[t][i], zl, zh);
                *(float2*)&Hs[(t*V + ub + i)*K + 2*kp] =
                    make_float2(zl * gk.x, zh * gk.y);
            }
        }
    __syncthreads();

    // LayerNorm stats (rotated k-scan: conflict-free)
    for (int p = tid; p < TT*V; p += 256) {
        float s = 0.f, s2 = 0.f;
        for (int kk = 0; kk < K; kk++) {
            int k = (kk + p) & 127;
            float val = Hs[p*K + k];
            s += val; s2 += val*val;
        }
        float m = s * (1.0f/K);
        float var = s2 * (1.0f/K) - m*m;
        mu_s[p] = m;
        rs_s[p] = rsqrtf(var + 1e-5f);
    }
    __syncthreads();

    const size_t obase = ((size_t)(b*T + tt*TT))*V*K;
    for (int lin = tid; lin < TT*V*K; lin += 256) {
        int r = lin >> 7, kk = lin & 127;
        float val = (Hs[lin] - mu_s[r]) * rs_s[r];
        out[obase + lin] = val * l2w[kk] + l2b[kk];
    }
}

// ---------------- launch ----------------------------------------------------
extern "C" void kernel_launch(void* const* d_in, const int* in_sizes, int n_in,
                              void* d_out, int out_size) {
    const float* x    = (const float*)d_in[0];
    const float* A    = (const float*)d_in[1];
    const float* lam  = (const float*)d_in[2];
    const float* phiw = (const float*)d_in[3];
    const float* phib = (const float*)d_in[4];
    const float* thw  = (const float*)d_in[5];
    const float* thb  = (const float*)d_in[6];
    const float* kapw = (const float*)d_in[7];
    const float* kapb = (const float*)d_in[8];
    const float* xiw  = (const float*)d_in[9];
    const float* xib  = (const float*)d_in[10];
    const float* qw   = (const float*)d_in[11];
    const float* qb   = (const float*)d_in[12];
    const float* kw   = (const float*)d_in[13];
    const float* kb   = (const float*)d_in[14];
    const float* c1w  = (const float*)d_in[15];
    const float* c1b  = (const float*)d_in[16];
    const float* l1w  = (const float*)d_in[17];
    const float* l1b  = (const float*)d_in[18];
    const float* c2w  = (const float*)d_in[19];
    const float* c2b  = (const float*)d_in[20];
    const float* l2w  = (const float*)d_in[21];
    const float* l2b  = (const float*)d_in[22];
    float* out = (float*)d_out;

    size_t sm2  = (size_t)(3200 + 16384) * 4;
    size_t sm3  = (size_t)(16384 + 8448) * 4;
    size_t sm4  = (size_t)(4*3200 + 2*4096 + 512 + 32) * 4;
    size_t sm56 = (size_t)(12800 + 3328 + 2048 + 3200 + 3200 + 100 + 108) * 4;

    cudaFuncSetAttribute(k2_small,  cudaFuncAttributeMaxDynamicSharedMemorySize, (int)sm2);
    cudaFuncSetAttribute(k3_atilde, cudaFuncAttributeMaxDynamicSharedMemorySize, (int)sm3);
    cudaFuncSetAttribute(k4_gate,   cudaFuncAttributeMaxDynamicSharedMemorySize, (int)sm4);
    cudaFuncSetAttribute(k56_fused, cudaFuncAttributeMaxDynamicSharedMemorySize, (int)sm56);

    k1_xbar<<<B*V, 128>>>(x);
    k2_small<<<B, 256, sm2>>>(phiw, phib, thw, thb, xiw, xib);
    k3_atilde<<<B*10, 256, sm3>>>(A, lam, kapw, kapb);
    k4_gate<<<B, 512, sm4>>>(qw, qb, kw, kb, c1w, c1b, l1w, l1b, c2w, c2b);
    k56_fused<<<B*32, 256, sm56>>>(x, xiw, xib, l2w, l2b, out);
}

// round 17
// speedup vs baseline: 2.4943x; 1.0737x over previous
#include <cuda_runtime.h>
#include <math.h>

#define B 64
#define T 128
#define V 25
#define C 128
#define K 128
#define R 32

// ---------------- scratch (device globals; no allocations allowed) ----------
__device__ float g_xbar[B*V*C];
__device__ float g_phi [B*V*K];
__device__ float g_theta[B*V*K];
__device__ float g_Hbar[B*V*K];
__device__ float g_Atil[B*V*V*K];      // [b][u][v][k]
__device__ float g_gate[B*K];

// f32x2 packed FMA (SASS FFMA2) -- exact fp32, 2x FFMA-pipe rate
__device__ __forceinline__ unsigned long long fma2(unsigned long long a,
                                                   unsigned long long b,
                                                   unsigned long long c) {
    unsigned long long d;
    asm("fma.rn.f32x2 %0, %1, %2, %3;" : "=l"(d) : "l"(a), "l"(b), "l"(c));
    return d;
}
__device__ __forceinline__ void unpack2(unsigned long long p, float& lo, float& hi) {
    asm("mov.b64 {%0,%1}, %2;" : "=f"(lo), "=f"(hi) : "l"(p));
}
__device__ __forceinline__ unsigned long long pack2(float v) {
    unsigned long long r;
    asm("mov.b64 %0, {%1,%1};" : "=l"(r) : "f"(v));
    return r;
}
__device__ __forceinline__ unsigned int smem_u32(const void* p) {
    unsigned int a;
    asm("{ .reg .u64 t; cvta.to.shared.u64 t, %1; cvt.u32.u64 %0, t; }"
        : "=r"(a) : "l"(p));
    return a;
}
__device__ __forceinline__ float tanh_fast(float v) {
    float r;
    asm("tanh.approx.f32 %0, %1;" : "=f"(r) : "f"(v));
    return r;
}
// cp.async of 16 BYTES (4 floats)
#define CP_ASYNC16(sa, gp) \
    asm volatile("cp.async.ca.shared.global [%0], [%1], 16;" \
                 :: "r"(sa), "l"(gp) : "memory")
#define CP_COMMIT() asm volatile("cp.async.commit_group;" ::: "memory")
#define CP_WAIT0()  asm volatile("cp.async.wait_group 0;" ::: "memory")

// ---------------- K1: xbar = mean_t x  (1600 blocks, coalesced) -------------
__global__ void k1_xbar(const float* __restrict__ x) {
    int bv = blockIdx.x;
    int c  = threadIdx.x;
    int b = bv / V, v = bv % V;
    const float* p = x + ((size_t)(b*T)*V + v)*C + c;
    float acc = 0.f;
#pragma unroll 8
    for (int t = 0; t < T; t++) acc += p[(size_t)t*V*C];
    g_xbar[bv*C + c] = acc * (1.0f/T);
}

// ---------------- K2: phi_x / theta_x / Hbar  (xbar @ W + b) ----------------
__global__ void k2_small(const float* __restrict__ pw, const float* __restrict__ pb,
                         const float* __restrict__ tw, const float* __restrict__ tb,
                         const float* __restrict__ xw, const float* __restrict__ xb2) {
    extern __shared__ float sm2[];
    float* xb_s = sm2;            // 3200
    float* W_s  = sm2 + 3200;     // 16384
    int b = blockIdx.x, tid = threadIdx.x;
    for (int lin = tid; lin < V*C; lin += 256) xb_s[lin] = g_xbar[b*V*C + lin];

    const float* Wp[3] = {pw, tw, xw};
    const float* Bp[3] = {pb, tb, xb2};
    float* Op[3];
    Op[0] = g_phi; Op[1] = g_theta; Op[2] = g_Hbar;

    for (int w = 0; w < 3; w++) {
        for (int lin = tid; lin < C*K; lin += 256) W_s[lin] = Wp[w][lin];
        __syncthreads();
        for (int task = tid; task < V*(K/4); task += 256) {
            int v  = task >> 5;
            int k4 = (task & 31) << 2;
            float4 acc = *(const float4*)&Bp[w][k4];
            for (int c = 0; c < C; c++) {
                float a = xb_s[v*C + c];
                float4 wv = *(const float4*)&W_s[c*K + k4];
                acc.x += a*wv.x; acc.y += a*wv.y; acc.z += a*wv.z; acc.w += a*wv.w;
            }
            *(float4*)&Op[w][b*V*K + v*K + k4] = acc;
        }
        __syncthreads();
    }
}

// ---------------- K3: A_tilde  (f32x2 GEMM, cp.async, 2 CTA/SM) -------------
__global__ void __launch_bounds__(256, 2) k3_atilde(
        const float* __restrict__ A, const float* __restrict__ lam_p,
        const float* __restrict__ kw, const float* __restrict__ kb) {
    extern __shared__ float sm3[];
    float* kap_s = sm3;            // 128*128 = 16384
    float* F_s   = sm3 + 16384;    // 64*132  = 8448 (also reused for A slice)
    int b      = blockIdx.x / 10;
    int pchunk = blockIdx.x % 10;
    int tid = threadIdx.x;
    int p0 = pchunk * 64;
    unsigned int kap_sa = smem_u32(kap_s);

    for (int lin = tid; lin < 4096; lin += 256) {
        int m = lin >> 5, f4 = (lin & 31) << 2;
        CP_ASYNC16(kap_sa + (m*128 + f4)*4, &kw[m*K + f4]);
    }
    CP_COMMIT();

    for (int lin = tid; lin < 64*128; lin += 256) {
        int p = lin >> 7, m = lin & 127;
        int pair = p0 + p;
        float f = 0.f;
        if (pair < V*V) {
            int i = pair / V, j = pair % V;
            f = tanh_fast(g_phi[(b*V+i)*K + m] - g_theta[(b*V+j)*K + m]);
        }
        F_s[p*132 + m] = f;
    }
    CP_WAIT0();
    __syncthreads();

    int kq = tid & 31;
    int pg = tid >> 5;
    int k0 = kq * 4;

    unsigned long long acc[8][2];
#pragma unroll
    for (int p = 0; p < 8; p++) { acc[p][0] = 0ull; acc[p][1] = 0ull; }

    for (int m = 0; m < K; m += 4) {
        ulonglong2 q0 = *(const ulonglong2*)&kap_s[(m+0)*128 + k0];
        ulonglong2 q1 = *(const ulonglong2*)&kap_s[(m+1)*128 + k0];
        ulonglong2 q2 = *(const ulonglong2*)&kap_s[(m+2)*128 + k0];
        ulonglong2 q3 = *(const ulonglong2*)&kap_s[(m+3)*128 + k0];
#pragma unroll
        for (int p = 0; p < 8; p++) {
            float4 f4 = *(const float4*)&F_s[(pg*8 + p)*132 + m];
            unsigned long long f0 = pack2(f4.x);
            unsigned long long f1 = pack2(f4.y);
            unsigned long long f2 = pack2(f4.z);
            unsigned long long f3 = pack2(f4.w);
            acc[p][0] = fma2(f0, q0.x, acc[p][0]);
            acc[p][1] = fma2(f0, q0.y, acc[p][1]);
            acc[p][0] = fma2(f1, q1.x, acc[p][0]);
            acc[p][1] = fma2(f1, q1.y, acc[p][1]);
            acc[p][0] = fma2(f2, q2.x, acc[p][0]);
            acc[p][1] = fma2(f2, q2.y, acc[p][1]);
            acc[p][0] = fma2(f3, q3.x, acc[p][0]);
            acc[p][1] = fma2(f3, q3.y, acc[p][1]);
        }
    }
    __syncthreads();

    for (int lin = tid; lin < 64*128; lin += 256) {
        int p = lin & 63, k = lin >> 6;
        float av = 0.f;
        if (p0 + p < V*V) av = A[(size_t)k*(V*V) + p0 + p];
        F_s[p*132 + k] = av;
    }
    __syncthreads();

    float lamv = *lam_p;
    float4 kb4 = *(const float4*)&kb[k0];
#pragma unroll
    for (int p = 0; p < 8; p++) {
        int pair = p0 + pg*8 + p;
        if (pair < V*V) {
            int i = pair / V, j = pair % V;
            float r0, r1, r2, r3;
            unpack2(acc[p][0], r0, r1);
            unpack2(acc[p][1], r2, r3);
            float4 a4 = *(const float4*)&F_s[(pg*8 + p)*132 + k0];
            float4 o;
            o.x = a4.x + lamv*(r0 + kb4.x);
            o.y = a4.y + lamv*(r1 + kb4.y);
            o.z = a4.z + lamv*(r2 + kb4.z);
            o.w = a4.w + lamv*(r3 + kb4.w);
            *(float4*)&g_Atil[((size_t)(b*V + i)*V + j)*K + k0] = o;
        }
    }
}

// ---------------- K4: gate[b][k] --------------------------------------------
__global__ void __launch_bounds__(512) k4_gate(
        const float* __restrict__ qw, const float* __restrict__ qb,
        const float* __restrict__ kw, const float* __restrict__ kb,
        const float* __restrict__ c1w, const float* __restrict__ c1b,
        const float* __restrict__ l1w, const float* __restrict__ l1b,
        const float* __restrict__ c2w, const float* __restrict__ c2b) {
    extern __shared__ float sm4[];
    float* Hb_s = sm4;
    float* Zb_s = Hb_s + 3200;
    float* XQ_s = Zb_s + 3200;
    float* XK_s = XQ_s + 3200;
    float* qw_s = XK_s + 3200;
    float* kw_s = qw_s + 4096;
    float* ca_s = kw_s + 4096;
    float* c1_s = ca_s + 512;

    int b = blockIdx.x, tid = threadIdx.x;
    int k = tid & 127, uh = tid >> 7;
    for (int lin = tid; lin < V*K; lin += 512) Hb_s[lin] = g_Hbar[b*V*K + lin];
    __syncthreads();

    int u_lo = (uh == 0) ? 0 : (7 + 6*(uh-1));
    int nu   = (uh == 0) ? 7 : 6;

    for (int ui = 0; ui < nu; ui++) {
        int u = u_lo + ui;
        float acc = 0.f;
        const float* ap = g_Atil + ((size_t)(b*V + u)*V)*K + k;
#pragma unroll
        for (int v = 0; v < V; v++) acc += ap[v*K] * Hb_s[v*K + k];
        Zb_s[u*K + k] = acc;
    }
    __syncthreads();

    float accq[7], acck[7];
    for (int ui = 0; ui < nu; ui++) { accq[ui] = qb[k]; acck[ui] = kb[k]; }
    for (int mc = 0; mc < K; mc += 32) {
        for (int lin = tid; lin < 32*128; lin += 512) {
            int mm = lin >> 7, kk = lin & 127;
            qw_s[lin] = qw[(mc + mm)*K + kk];
            kw_s[lin] = kw[(mc + mm)*K + kk];
        }
        __syncthreads();
        for (int ui = 0; ui < nu; ui++) {
            int u = u_lo + ui;
            float aq = accq[ui], ak = acck[ui];
#pragma unroll
            for (int mm = 0; mm < 32; mm++) {
                float z = Zb_s[u*K + mc + mm];
                aq += z * qw_s[mm*128 + k];
                ak += z * kw_s[mm*128 + k];
            }
            accq[ui] = aq; acck[ui] = ak;
        }
        __syncthreads();
    }
    for (int ui = 0; ui < nu; ui++) {
        XQ_s[(u_lo+ui)*K + k] = accq[ui];
        XK_s[(u_lo+ui)*K + k] = acck[ui];
    }
    __syncthreads();

    const float inv_scale = 1.0f / sqrtf((float)T);
    float ca = 0.f;
    for (int ui = 0; ui < nu; ui++) {
        int u = u_lo + ui;
        float xq = XQ_s[u*K + k];
        float mx = -1e30f;
#pragma unroll
        for (int v = 0; v < V; v++) {
            float s = xq * XK_s[v*K + k] * inv_scale;
            mx = fmaxf(mx, s);
        }
        float den = 0.f, num = 0.f;
#pragma unroll
        for (int v = 0; v < V; v++) {
            float s = xq * XK_s[v*K + k] * inv_scale;
            float e = expf(s - mx);
            den += e;
            num += e * Hb_s[v*K + k];
        }
        ca += num / den;
    }
    ca_s[tid] = ca;
    __syncthreads();
    if (tid < 128)
        ca_s[tid] = (ca_s[tid] + ca_s[tid+128] + ca_s[tid+256] + ca_s[tid+384]) * (1.0f/V);
    __syncthreads();

    if (tid < R) {
        float t = c1b[tid];
        for (int kk = 0; kk < K; kk++) t += ca_s[kk] * c1w[kk*R + tid];
        float mu = t;
#pragma unroll
        for (int o = 16; o > 0; o >>= 1) mu += __shfl_xor_sync(0xffffffffu, mu, o);
        mu *= (1.0f/R);
        float d = t - mu;
        float var = d*d;
#pragma unroll
        for (int o = 16; o > 0; o >>= 1) var += __shfl_xor_sync(0xffffffffu, var, o);
        var *= (1.0f/R);
        float y = d * rsqrtf(var + 1e-5f) * l1w[tid] + l1b[tid];
        c1_s[tid] = 0.5f * y * (1.0f + erff(y * 0.70710678118654752f));
    }
    __syncthreads();

    if (tid < 128) {
        float g = c2b[k];
#pragma unroll
        for (int r = 0; r < R; r++) g += c1_s[r] * c2w[r*K + k];
        g_gate[b*K + k] = 1.0f / (1.0f + expf(-g));
    }
}

// ---------------- K56: fused H-GEMM + gated GCN + LN --------------------------
// Phase A: double-buffered cp.async (ws + x plain), in-register pack2.
//          thread = (kq->4k, vh->13v, ta->4 t-groups); acc[13][2] ULL.
// Phase B: NO smem staging -- direct coalesced LDG.128 of A_tilde (L2-hot),
//          no in-loop syncs. thread = (kq->4k, ug->8 u-groups); z[4][4][2].
#define TT 4
__global__ void __launch_bounds__(256, 2) k56_fused(
        const float* __restrict__ x,
        const float* __restrict__ xiw, const float* __restrict__ xib,
        const float* __restrict__ l2w, const float* __restrict__ l2b,
        float* __restrict__ out) {
    extern __shared__ float sm6[];
    float* Hs   = sm6;                 // 100*128 = 12800
    float* xs0  = Hs  + 12800;         // 104*16  = 1664 (padded rows)
    float* xs1  = xs0 + 1664;          // 1664
    float* ws0  = xs1 + 1664;          // 2048
    float* ws1  = ws0 + 2048;          // 2048
    float* mu_s = ws1 + 2048;          // 100
    float* rs_s = mu_s + 100;          // 100 (+8 pad)

    int b  = blockIdx.x >> 5;
    int tt = blockIdx.x & 31;
    int tid  = threadIdx.x;

    float* xsb[2] = {xs0, xs1};
    float* wsb[2] = {ws0, ws1};
    unsigned int xs_sa[2] = {smem_u32(xs0), smem_u32(xs1)};
    unsigned int ws_sa[2] = {smem_u32(ws0), smem_u32(ws1)};

    // ---------- Phase A ------------------------------------------------------
    int kq = tid & 31;                 // k quad: k0..k0+3
    int vh = (tid >> 5) & 1;           // v half
    int ta = tid >> 6;                 // t group 0..3
    int k0 = kq*4;
    int vbase = vh*13;                 // 0 or 13 (slot 25 is zero dummy)

    const size_t xbase = ((size_t)(b*T + tt*TT))*V*C;  // 100 contiguous rows

    // zero dummy slots (rows 25,51,77,103 of each buffer)
    for (int lin = tid; lin < 128; lin += 256) {
        int bu = lin >> 6, g = (lin >> 4) & 3, c = lin & 15;
        xsb[bu][(g*26 + 25)*16 + c] = 0.f;
    }

    // prologue: stage chunk 0 into buffer 0
    for (int lin = tid; lin < 512; lin += 256) {
        int c = lin >> 5, f4 = (lin & 31) << 2;
        CP_ASYNC16(ws_sa[0] + (c*128 + f4)*4, &xiw[c*K + f4]);
    }
    for (int lin = tid; lin < 400; lin += 256) {
        int r = lin >> 2, c4 = (lin & 3) << 2;
        int slot = (r/25)*26 + (r%25);
        CP_ASYNC16(xs_sa[0] + (slot*16 + c4)*4, &x[xbase + (size_t)r*C + c4]);
    }
    CP_COMMIT();
    CP_WAIT0();
    __syncthreads();

    unsigned long long acc[13][2];
#pragma unroll
    for (int v = 0; v < 13; v++) { acc[v][0] = 0ull; acc[v][1] = 0ull; }

    for (int ch = 0; ch < 8; ch++) {
        int cur = ch & 1, nxt = cur ^ 1;
        if (ch < 7) {
            int cc = (ch + 1) * 16;
            for (int lin = tid; lin < 512; lin += 256) {
                int c = lin >> 5, f4 = (lin & 31) << 2;
                CP_ASYNC16(ws_sa[nxt] + (c*128 + f4)*4, &xiw[(cc + c)*K + f4]);
            }
            for (int lin = tid; lin < 400; lin += 256) {
                int r = lin >> 2, c4 = (lin & 3) << 2;
                int slot = (r/25)*26 + (r%25);
                CP_ASYNC16(xs_sa[nxt] + (slot*16 + c4)*4,
                           &x[xbase + (size_t)r*C + cc + c4]);
            }
            CP_COMMIT();
        }
        const float* wsc = wsb[cur];
        const float* xsc = xsb[cur];
#pragma unroll
        for (int cg = 0; cg < 8; cg++) {
            int c0 = cg*2;
            ulonglong2 w0 = *(const ulonglong2*)&wsc[c0*128 + k0];
            ulonglong2 w1 = *(const ulonglong2*)&wsc[(c0+1)*128 + k0];
            const float* xr = &xsc[(ta*26 + vbase)*16 + c0];
#pragma unroll
            for (int v = 0; v < 13; v++) {
                unsigned long long x0 = pack2(xr[v*16]);
                unsigned long long x1 = pack2(xr[v*16 + 1]);
                acc[v][0] = fma2(x0, w0.x, acc[v][0]);
                acc[v][1] = fma2(x0, w0.y, acc[v][1]);
                acc[v][0] = fma2(x1, w1.x, acc[v][0]);
                acc[v][1] = fma2(x1, w1.y, acc[v][1]);
            }
        }
        if (ch < 7) CP_WAIT0();
        __syncthreads();
    }

    // write H tile (+bias) to smem; guard dummy row
    {
        float4 b4 = *(const float4*)&xib[k0];
#pragma unroll
        for (int v = 0; v < 13; v++) {
            int row = vbase + v;
            if (row < V) {
                float f0,f1,f2,f3;
                unpack2(acc[v][0], f0, f1);
                unpack2(acc[v][1], f2, f3);
                float4 o = make_float4(f0+b4.x, f1+b4.y, f2+b4.z, f3+b4.w);
                *(float4*)&Hs[(ta*V + row)*K + k0] = o;
            }
        }
    }
    __syncthreads();

    // ---------- Phase B: direct-LDG gated GCN --------------------------------
    int ug = tid >> 5;                 // u group 0..7
    int ubase = (ug == 0) ? 0 : (4 + 3*(ug-1));   // 0,4,7,10,...,22
    int ucnt  = (ug == 0) ? 4 : 3;

    const float* ap[4];
#pragma unroll
    for (int i = 0; i < 4; i++) {
        int uu = ubase + ((i < ucnt) ? i : (ucnt - 1));
        ap[i] = g_Atil + ((size_t)(b*V + uu)*V)*K + k0;
    }

    unsigned long long z[4][4][2];
#pragma unroll
    for (int t = 0; t < 4; t++)
#pragma unroll
        for (int i = 0; i < 4; i++) { z[t][i][0] = 0ull; z[t][i][1] = 0ull; }

#pragma unroll 5
    for (int v = 0; v < V; v++) {
        ulonglong2 h0 = *(const ulonglong2*)&Hs[(0*V + v)*K + k0];
        ulonglong2 h1 = *(const ulonglong2*)&Hs[(1*V + v)*K + k0];
        ulonglong2 h2 = *(const ulonglong2*)&Hs[(2*V + v)*K + k0];
        ulonglong2 h3 = *(const ulonglong2*)&Hs[(3*V + v)*K + k0];
#pragma unroll
        for (int i = 0; i < 4; i++) {
            ulonglong2 a = *(const ulonglong2*)&ap[i][(size_t)v*K];
            z[0][i][0] = fma2(h0.x, a.x, z[0][i][0]);
            z[0][i][1] = fma2(h0.y, a.y, z[0][i][1]);
            z[1][i][0] = fma2(h1.x, a.x, z[1][i][0]);
            z[1][i][1] = fma2(h1.y, a.y, z[1][i][1]);
            z[2][i][0] = fma2(h2.x, a.x, z[2][i][0]);
            z[2][i][1] = fma2(h2.y, a.y, z[2][i][1]);
            z[3][i][0] = fma2(h3.x, a.x, z[3][i][0]);
            z[3][i][1] = fma2(h3.y, a.y, z[3][i][1]);
        }
    }
    __syncthreads();   // all Hs reads done before overwrite

    float4 gk = *(const float4*)&g_gate[b*K + k0];
#pragma unroll
    for (int t = 0; t < 4; t++)
#pragma unroll
        for (int i = 0; i < 4; i++) {
            if (i < ucnt) {
                float z0, z1, z2, z3;
                unpack2(z[t][i][0], z0, z1);
                unpack2(z[t][i][1], z2, z3);
                float4 o = make_float4(z0*gk.x, z1*gk.y, z2*gk.z, z3*gk.w);
                *(float4*)&Hs[(t*V + ubase + i)*K + k0] = o;
            }
        }
    __syncthreads();

    // LayerNorm stats (rotated k-scan: conflict-free)
    for (int p = tid; p < TT*V; p += 256) {
        float s = 0.f, s2 = 0.f;
        for (int kk = 0; kk < K; kk++) {
            int k = (kk + p) & 127;
            float val = Hs[p*K + k];
            s += val; s2 += val*val;
        }
        float m = s * (1.0f/K);
        float var = s2 * (1.0f/K) - m*m;
        mu_s[p] = m;
        rs_s[p] = rsqrtf(var + 1e-5f);
    }
    __syncthreads();

    const size_t obase = ((size_t)(b*T + tt*TT))*V*K;
    for (int lin = tid; lin < TT*V*K; lin += 256) {
        int r = lin >> 7, kk = lin & 127;
        float val = (Hs[lin] - mu_s[r]) * rs_s[r];
        out[obase + lin] = val * l2w[kk] + l2b[kk];
    }
}

// ---------------- launch ----------------------------------------------------
extern "C" void kernel_launch(void* const* d_in, const int* in_sizes, int n_in,
                              void* d_out, int out_size) {
    const float* x    = (const float*)d_in[0];
    const float* A    = (const float*)d_in[1];
    const float* lam  = (const float*)d_in[2];
    const float* phiw = (const float*)d_in[3];
    const float* phib = (const float*)d_in[4];
    const float* thw  = (const float*)d_in[5];
    const float* thb  = (const float*)d_in[6];
    const float* kapw = (const float*)d_in[7];
    const float* kapb = (const float*)d_in[8];
    const float* xiw  = (const float*)d_in[9];
    const float* xib  = (const float*)d_in[10];
    const float* qw   = (const float*)d_in[11];
    const float* qb   = (const float*)d_in[12];
    const float* kw   = (const float*)d_in[13];
    const float* kb   = (const float*)d_in[14];
    const float* c1w  = (const float*)d_in[15];
    const float* c1b  = (const float*)d_in[16];
    const float* l1w  = (const float*)d_in[17];
    const float* l1b  = (const float*)d_in[18];
    const float* c2w  = (const float*)d_in[19];
    const float* c2b  = (const float*)d_in[20];
    const float* l2w  = (const float*)d_in[21];
    const float* l2b  = (const float*)d_in[22];
    float* out = (float*)d_out;

    size_t sm2  = (size_t)(3200 + 16384) * 4;
    size_t sm3  = (size_t)(16384 + 8448) * 4;
    size_t sm4  = (size_t)(4*3200 + 2*4096 + 512 + 32) * 4;
    size_t sm56 = (size_t)(12800 + 2*1664 + 2*2048 + 100 + 108) * 4;

    cudaFuncSetAttribute(k2_small,  cudaFuncAttributeMaxDynamicSharedMemorySize, (int)sm2);
    cudaFuncSetAttribute(k3_atilde, cudaFuncAttributeMaxDynamicSharedMemorySize, (int)sm3);
    cudaFuncSetAttribute(k4_gate,   cudaFuncAttributeMaxDynamicSharedMemorySize, (int)sm4);
    cudaFuncSetAttribute(k56_fused, cudaFuncAttributeMaxDynamicSharedMemorySize, (int)sm56);

    k1_xbar<<<B*V, 128>>>(x);
    k2_small<<<B, 256, sm2>>>(phiw, phib, thw, thb, xiw, xib);
    k3_atilde<<<B*10, 256, sm3>>>(A, lam, kapw, kapb);
    k4_gate<<<B, 512, sm4>>>(qw, qb, kw, kb, c1w, c1b, l1w, l1b, c2w, c2b);
    k56_fused<<<B*32, 256, sm56>>>(x, xiw, xib, l2w, l2b, out);
}